// round 4
// baseline (speedup 1.0000x reference)
#include <cuda_runtime.h>
#include <mma.h>
#include <cstdint>

using namespace nvcuda;

// Problem constants
#define BATCH 2
#define SEQ   2048
#define HEADS 16
#define HD    64
#define EMB   1024
#define MROWS (BATCH*SEQ)          // 4096
#define QKVN  (3*EMB)              // 3072

// Scratch (allocation-free rule: __device__ globals)
__device__ float g_qkv[(size_t)MROWS * QKVN];   // 50.3 MB
__device__ float g_attn[(size_t)MROWS * EMB];   // 16.8 MB

__device__ __forceinline__ float to_tf32(float x) {
    float y;
    asm("cvt.rna.tf32.f32 %0, %1;" : "=f"(y) : "f"(x));
    return y;
}

// ---------------------------------------------------------------------------
// 3xTF32 GEMM: C[M][Ndim] = A[M][1024] * B[1024][Ndim], M=4096, near-fp32.
// A = A_hi + A_lo, B = B_hi + B_lo (tf32 split);
// acc += A_hi*B_hi + A_lo*B_hi + A_hi*B_lo.
// BM=128, BN=128, BK=16, 256 threads (8 warps), warp tile 64x32.
// ---------------------------------------------------------------------------
__global__ __launch_bounds__(256) void gemm_3xtf32(
    const float* __restrict__ A,
    const float* __restrict__ B,
    float* __restrict__ C,
    int Ndim)
{
    __shared__ float AsH[128][24];
    __shared__ float AsL[128][24];
    __shared__ float BsH[16][136];
    __shared__ float BsL[16][136];

    const int tid = threadIdx.x;
    const int warp = tid >> 5;
    const int warp_m = warp >> 2;   // 0..1 -> 64-row slab
    const int warp_n = warp & 3;    // 0..3 -> 32-col slab
    const int m0 = blockIdx.y * 128;
    const int n0 = blockIdx.x * 128;

    wmma::fragment<wmma::accumulator, 16, 16, 8, float> acc[4][2];
    #pragma unroll
    for (int mt = 0; mt < 4; mt++)
        #pragma unroll
        for (int nt = 0; nt < 2; nt++)
            wmma::fill_fragment(acc[mt][nt], 0.0f);

    for (int k0 = 0; k0 < EMB; k0 += 16) {
        // A tile 128x16, split into hi/lo
        {
            const int ar = tid >> 2;
            const int ac = (tid & 3) * 4;
            #pragma unroll
            for (int p = 0; p < 2; p++) {
                const int r = ar + p * 64;
                float4 v = *(const float4*)&A[(size_t)(m0 + r) * EMB + k0 + ac];
                float h0 = to_tf32(v.x), h1 = to_tf32(v.y), h2 = to_tf32(v.z), h3 = to_tf32(v.w);
                AsH[r][ac + 0] = h0; AsL[r][ac + 0] = to_tf32(v.x - h0);
                AsH[r][ac + 1] = h1; AsL[r][ac + 1] = to_tf32(v.y - h1);
                AsH[r][ac + 2] = h2; AsL[r][ac + 2] = to_tf32(v.z - h2);
                AsH[r][ac + 3] = h3; AsL[r][ac + 3] = to_tf32(v.w - h3);
            }
        }
        // B tile 16x128, split into hi/lo
        {
            const int br = tid >> 5;
            const int bc = (tid & 31) * 4;
            #pragma unroll
            for (int p = 0; p < 2; p++) {
                const int r = br + p * 8;
                float4 v = *(const float4*)&B[(size_t)(k0 + r) * Ndim + n0 + bc];
                float h0 = to_tf32(v.x), h1 = to_tf32(v.y), h2 = to_tf32(v.z), h3 = to_tf32(v.w);
                BsH[r][bc + 0] = h0; BsL[r][bc + 0] = to_tf32(v.x - h0);
                BsH[r][bc + 1] = h1; BsL[r][bc + 1] = to_tf32(v.y - h1);
                BsH[r][bc + 2] = h2; BsL[r][bc + 2] = to_tf32(v.z - h2);
                BsH[r][bc + 3] = h3; BsL[r][bc + 3] = to_tf32(v.w - h3);
            }
        }
        __syncthreads();

        #pragma unroll
        for (int ks = 0; ks < 2; ks++) {
            wmma::fragment<wmma::matrix_a, 16, 16, 8, wmma::precision::tf32, wmma::row_major> afH[4], afL[4];
            wmma::fragment<wmma::matrix_b, 16, 16, 8, wmma::precision::tf32, wmma::row_major> bfH[2], bfL[2];
            #pragma unroll
            for (int mt = 0; mt < 4; mt++) {
                wmma::load_matrix_sync(afH[mt], &AsH[warp_m * 64 + mt * 16][ks * 8], 24);
                wmma::load_matrix_sync(afL[mt], &AsL[warp_m * 64 + mt * 16][ks * 8], 24);
            }
            #pragma unroll
            for (int nt = 0; nt < 2; nt++) {
                wmma::load_matrix_sync(bfH[nt], &BsH[ks * 8][warp_n * 32 + nt * 16], 136);
                wmma::load_matrix_sync(bfL[nt], &BsL[ks * 8][warp_n * 32 + nt * 16], 136);
            }
            #pragma unroll
            for (int mt = 0; mt < 4; mt++)
                #pragma unroll
                for (int nt = 0; nt < 2; nt++) {
                    wmma::mma_sync(acc[mt][nt], afL[mt], bfH[nt], acc[mt][nt]);
                    wmma::mma_sync(acc[mt][nt], afH[mt], bfL[nt], acc[mt][nt]);
                    wmma::mma_sync(acc[mt][nt], afH[mt], bfH[nt], acc[mt][nt]);
                }
        }
        __syncthreads();
    }

    #pragma unroll
    for (int mt = 0; mt < 4; mt++)
        #pragma unroll
        for (int nt = 0; nt < 2; nt++)
            wmma::store_matrix_sync(
                &C[(size_t)(m0 + warp_m * 64 + mt * 16) * Ndim + n0 + warp_n * 32 + nt * 16],
                acc[mt][nt], Ndim, wmma::mem_row_major);
}

// ---------------------------------------------------------------------------
// RoPE: in-place on g_qkv q,k columns (0..2047). One float4 = two rotation pairs.
// ---------------------------------------------------------------------------
__global__ __launch_bounds__(256) void rope_kernel(const float* __restrict__ freqs)
{
    const int idx = blockIdx.x * 256 + threadIdx.x;           // over 4096*512 float4s
    const int row = idx >> 9;              // 512 float4 per row (2048 cols)
    const int col = (idx & 511) * 4;
    float* p = &g_qkv[(size_t)row * QKVN + col];
    float4 v = *(float4*)p;
    const int l = row & (SEQ - 1);
    const int d0 = col & (HD - 1);
    const float* f = &freqs[(size_t)l * HD + d0];
    float f0 = f[0], f1 = f[1], f2 = f[2], f3 = f[3];
    float4 o;
    o.x = v.x * f0 - v.y * f1;
    o.y = v.y * f0 + v.x * f1;
    o.z = v.z * f2 - v.w * f3;
    o.w = v.w * f2 + v.z * f3;
    *(float4*)p = o;
}

// ---------------------------------------------------------------------------
// Flash attention with wmma tf32. Block: 128 q-rows, one (b,h). 512 threads.
// Iterate 64-key tiles: S = Q@K^T (wmma) -> shared; +bias, online softmax;
// P (tf32) -> PV (wmma) -> alpha-rescaled O in shared.
// ---------------------------------------------------------------------------
#define QLD 72
__global__ __launch_bounds__(512) void attn_kernel(const float* __restrict__ bias)
{
    extern __shared__ float sm[];
    float* Qs = sm;                     // 128 x QLD
    float* Ks = Qs + 128 * QLD;         // 64 x QLD
    float* Vs = Ks + 64 * QLD;          // 64 x QLD
    float* Ss = Vs + 64 * QLD;          // 128 x QLD  (S -> P -> PVout)
    float* Os = Ss + 128 * QLD;         // 128 x 64

    const int tid = threadIdx.x;
    const int warp = tid >> 5;          // 0..15
    const int warp_qm = warp >> 1;      // 0..7 -> 16-row slab
    const int warp_n = warp & 1;        // 0..1 -> 32-col slab
    const int q0 = blockIdx.x * 128;
    const int h  = blockIdx.y;
    const int b  = blockIdx.z;
    const float scale = 0.125f;

    // Load Q (pre-scaled, tf32), zero O
    {
        const int r = tid >> 2;                 // 0..127
        const int c0 = (tid & 3) * 16;
        const float* src = &g_qkv[(size_t)(b * SEQ + q0 + r) * QKVN + h * HD + c0];
        #pragma unroll
        for (int i = 0; i < 4; i++) {
            float4 v = *(const float4*)&src[i * 4];
            Qs[r * QLD + c0 + i * 4 + 0] = to_tf32(v.x * scale);
            Qs[r * QLD + c0 + i * 4 + 1] = to_tf32(v.y * scale);
            Qs[r * QLD + c0 + i * 4 + 2] = to_tf32(v.z * scale);
            Qs[r * QLD + c0 + i * 4 + 3] = to_tf32(v.w * scale);
        }
        #pragma unroll
        for (int i = 0; i < 16; i++) Os[r * 64 + c0 + i] = 0.0f;
    }

    const int sr = tid >> 2;            // softmax row 0..127
    const int sc = (tid & 3) * 16;      // softmax col slab
    float m_r = -1e30f, l_r = 0.0f;

    for (int kt = 0; kt < SEQ / 64; kt++) {
        // Load K,V tiles (64 x 64)
        {
            const int r = tid >> 3;               // 0..63
            const int c0 = (tid & 7) * 8;
            const size_t base = (size_t)(b * SEQ + kt * 64 + r) * QKVN + h * HD + c0;
            #pragma unroll
            for (int i = 0; i < 2; i++) {
                float4 kv = *(const float4*)&g_qkv[base + EMB + i * 4];
                Ks[r * QLD + c0 + i * 4 + 0] = to_tf32(kv.x);
                Ks[r * QLD + c0 + i * 4 + 1] = to_tf32(kv.y);
                Ks[r * QLD + c0 + i * 4 + 2] = to_tf32(kv.z);
                Ks[r * QLD + c0 + i * 4 + 3] = to_tf32(kv.w);
                float4 vv = *(const float4*)&g_qkv[base + 2 * EMB + i * 4];
                Vs[r * QLD + c0 + i * 4 + 0] = to_tf32(vv.x);
                Vs[r * QLD + c0 + i * 4 + 1] = to_tf32(vv.y);
                Vs[r * QLD + c0 + i * 4 + 2] = to_tf32(vv.z);
                Vs[r * QLD + c0 + i * 4 + 3] = to_tf32(vv.w);
            }
        }
        __syncthreads();

        // S = Q @ K^T : warp computes rows [16*warp_qm, +16), cols [32*warp_n, +32)
        {
            wmma::fragment<wmma::accumulator, 16, 16, 8, float> sc_acc[2];
            wmma::fill_fragment(sc_acc[0], 0.0f);
            wmma::fill_fragment(sc_acc[1], 0.0f);
            #pragma unroll
            for (int kk = 0; kk < 8; kk++) {
                wmma::fragment<wmma::matrix_a, 16, 16, 8, wmma::precision::tf32, wmma::row_major> af;
                wmma::load_matrix_sync(af, &Qs[(warp_qm * 16) * QLD + kk * 8], QLD);
                #pragma unroll
                for (int nt = 0; nt < 2; nt++) {
                    wmma::fragment<wmma::matrix_b, 16, 16, 8, wmma::precision::tf32, wmma::col_major> bf;
                    wmma::load_matrix_sync(bf, &Ks[(warp_n * 32 + nt * 16) * QLD + kk * 8], QLD);
                    wmma::mma_sync(sc_acc[nt], af, bf, sc_acc[nt]);
                }
            }
            #pragma unroll
            for (int nt = 0; nt < 2; nt++)
                wmma::store_matrix_sync(&Ss[(warp_qm * 16) * QLD + warp_n * 32 + nt * 16],
                                        sc_acc[nt], QLD, wmma::mem_row_major);
        }
        __syncthreads();

        // Online softmax: 4 threads per row, 16 cols each
        float alpha;
        {
            float sv[16];
            const float4* bp = (const float4*)&bias[((size_t)h * SEQ + q0 + sr) * SEQ + kt * 64 + sc];
            #pragma unroll
            for (int j = 0; j < 4; j++) {
                float4 bb = __ldcs(bp + j);
                sv[j * 4 + 0] = Ss[sr * QLD + sc + j * 4 + 0] + bb.x;
                sv[j * 4 + 1] = Ss[sr * QLD + sc + j * 4 + 1] + bb.y;
                sv[j * 4 + 2] = Ss[sr * QLD + sc + j * 4 + 2] + bb.z;
                sv[j * 4 + 3] = Ss[sr * QLD + sc + j * 4 + 3] + bb.w;
            }
            float tm = sv[0];
            #pragma unroll
            for (int j = 1; j < 16; j++) tm = fmaxf(tm, sv[j]);
            tm = fmaxf(tm, __shfl_xor_sync(0xffffffffu, tm, 1));
            tm = fmaxf(tm, __shfl_xor_sync(0xffffffffu, tm, 2));
            const float mn = fmaxf(m_r, tm);
            alpha = __expf(m_r - mn);
            m_r = mn;
            float ts = 0.0f;
            #pragma unroll
            for (int j = 0; j < 16; j++) { sv[j] = __expf(sv[j] - mn); ts += sv[j]; }
            ts += __shfl_xor_sync(0xffffffffu, ts, 1);
            ts += __shfl_xor_sync(0xffffffffu, ts, 2);
            l_r = l_r * alpha + ts;
            #pragma unroll
            for (int j = 0; j < 16; j++) Ss[sr * QLD + sc + j] = to_tf32(sv[j]);
        }
        __syncthreads();

        // PV = P @ V : same warp tiling (cols are d now)
        {
            wmma::fragment<wmma::accumulator, 16, 16, 8, float> pv_acc[2];
            wmma::fill_fragment(pv_acc[0], 0.0f);
            wmma::fill_fragment(pv_acc[1], 0.0f);
            #pragma unroll
            for (int kk = 0; kk < 8; kk++) {
                wmma::fragment<wmma::matrix_a, 16, 16, 8, wmma::precision::tf32, wmma::row_major> af;
                wmma::load_matrix_sync(af, &Ss[(warp_qm * 16) * QLD + kk * 8], QLD);
                #pragma unroll
                for (int nt = 0; nt < 2; nt++) {
                    wmma::fragment<wmma::matrix_b, 16, 16, 8, wmma::precision::tf32, wmma::row_major> bf;
                    wmma::load_matrix_sync(bf, &Vs[(kk * 8) * QLD + warp_n * 32 + nt * 16], QLD);
                    wmma::mma_sync(pv_acc[nt], af, bf, pv_acc[nt]);
                }
            }
            __syncthreads();   // all P reads complete before reusing Ss as PV output
            #pragma unroll
            for (int nt = 0; nt < 2; nt++)
                wmma::store_matrix_sync(&Ss[(warp_qm * 16) * QLD + warp_n * 32 + nt * 16],
                                        pv_acc[nt], QLD, wmma::mem_row_major);
        }
        __syncthreads();

        // O = O * alpha + PV
        #pragma unroll
        for (int j = 0; j < 16; j++)
            Os[sr * 64 + sc + j] = Os[sr * 64 + sc + j] * alpha + Ss[sr * QLD + sc + j];
        // next-iter K/V-load sync orders Ss reuse
    }

    __syncthreads();
    // Normalize and write out
    {
        const float inv = 1.0f / l_r;
        float* dst = &g_attn[(size_t)(b * SEQ + q0 + sr) * EMB + h * HD + sc];
        #pragma unroll
        for (int i = 0; i < 4; i++) {
            float4 o;
            o.x = Os[sr * 64 + sc + i * 4 + 0] * inv;
            o.y = Os[sr * 64 + sc + i * 4 + 1] * inv;
            o.z = Os[sr * 64 + sc + i * 4 + 2] * inv;
            o.w = Os[sr * 64 + sc + i * 4 + 3] * inv;
            *(float4*)&dst[i * 4] = o;
        }
    }
}

// ---------------------------------------------------------------------------
// Proj bias add: out[row][col] += b_proj[col]
// ---------------------------------------------------------------------------
__global__ __launch_bounds__(256) void bias_add(float* __restrict__ out,
                                                const float* __restrict__ bproj)
{
    const int idx = blockIdx.x * 256 + threadIdx.x;   // over 4096*256 float4
    const int c4 = (idx & 255) * 4;
    float4 v = *(float4*)&out[(size_t)idx * 4];
    const float4 bp = *(const float4*)&bproj[c4];
    v.x += bp.x; v.y += bp.y; v.z += bp.z; v.w += bp.w;
    *(float4*)&out[(size_t)idx * 4] = v;
}

// ---------------------------------------------------------------------------
extern "C" void kernel_launch(void* const* d_in, const int* in_sizes, int n_in,
                              void* d_out, int out_size)
{
    const float* x      = (const float*)d_in[0];  // (2,2048,1024)
    const float* freqs  = (const float*)d_in[1];  // (2048,32,2)
    const float* bias   = (const float*)d_in[2];  // (1,16,2048,2048)
    const float* w_qkv  = (const float*)d_in[3];  // (1024,3072)
    const float* w_proj = (const float*)d_in[4];  // (1024,1024)
    const float* b_proj = (const float*)d_in[5];  // (1024,)
    float* out = (float*)d_out;                   // (2,2048,1024)

    float* qkv_ptr;  cudaGetSymbolAddress((void**)&qkv_ptr, g_qkv);
    float* attn_ptr; cudaGetSymbolAddress((void**)&attn_ptr, g_attn);

    const int attn_smem = (128 * QLD * 2 + 64 * QLD * 2 + 128 * 64) * sizeof(float); // 143360
    cudaFuncSetAttribute(attn_kernel, cudaFuncAttributeMaxDynamicSharedMemorySize, attn_smem);

    // 1) QKV GEMM (3xTF32, near-fp32) -> g_qkv
    gemm_3xtf32<<<dim3(QKVN / 128, MROWS / 128), 256>>>(x, w_qkv, qkv_ptr, QKVN);
    // 2) RoPE in place on q,k
    rope_kernel<<<(MROWS * 2048 / 4) / 256, 256>>>(freqs);
    // 3) attention -> g_attn
    attn_kernel<<<dim3(SEQ / 128, HEADS, BATCH), 512, attn_smem>>>(bias);
    // 4) proj GEMM (3xTF32) -> out
    gemm_3xtf32<<<dim3(EMB / 128, MROWS / 128), 256>>>(attn_ptr, w_proj, out, EMB);
    // 5) + b_proj
    bias_add<<<(MROWS * EMB / 4) / 256, 256>>>(out, b_proj);
}

// round 5
// speedup vs baseline: 1.2389x; 1.2389x over previous
#include <cuda_runtime.h>
#include <mma.h>
#include <cstdint>

using namespace nvcuda;

// Problem constants
#define BATCH 2
#define SEQ   2048
#define HEADS 16
#define HD    64
#define EMB   1024
#define MROWS (BATCH*SEQ)          // 4096
#define QKVN  (3*EMB)              // 3072

// Scratch (allocation-free rule: __device__ globals)
__device__ float g_qkv[(size_t)MROWS * QKVN];   // 50.3 MB
__device__ float g_attn[(size_t)MROWS * EMB];   // 16.8 MB

__device__ __forceinline__ float to_tf32(float x) {
    float y;
    asm("cvt.rna.tf32.f32 %0, %1;" : "=f"(y) : "f"(x));
    return y;
}

// Raw tensor-core mma: D(16x8,f32) += A(16x8,tf32,row) * B(8x8,tf32,col)
__device__ __forceinline__ void mma_16n8k8(float c[4], const uint32_t a[4], const uint32_t b[2]) {
    asm volatile(
        "mma.sync.aligned.m16n8k8.row.col.f32.tf32.tf32.f32 "
        "{%0,%1,%2,%3}, {%4,%5,%6,%7}, {%8,%9}, {%0,%1,%2,%3};"
        : "+f"(c[0]), "+f"(c[1]), "+f"(c[2]), "+f"(c[3])
        : "r"(a[0]), "r"(a[1]), "r"(a[2]), "r"(a[3]), "r"(b[0]), "r"(b[1]));
}

// ---------------------------------------------------------------------------
// 3xTF32 GEMM: C[M][Ndim] = A[M][1024] * B[1024][Ndim], M=4096, near-fp32.
// (unchanged from round 4 — measured 370us QKV / ~125us proj, tensor=45.6%)
// ---------------------------------------------------------------------------
__global__ __launch_bounds__(256) void gemm_3xtf32(
    const float* __restrict__ A,
    const float* __restrict__ B,
    float* __restrict__ C,
    int Ndim)
{
    __shared__ float AsH[128][24];
    __shared__ float AsL[128][24];
    __shared__ float BsH[16][136];
    __shared__ float BsL[16][136];

    const int tid = threadIdx.x;
    const int warp = tid >> 5;
    const int warp_m = warp >> 2;
    const int warp_n = warp & 3;
    const int m0 = blockIdx.y * 128;
    const int n0 = blockIdx.x * 128;

    wmma::fragment<wmma::accumulator, 16, 16, 8, float> acc[4][2];
    #pragma unroll
    for (int mt = 0; mt < 4; mt++)
        #pragma unroll
        for (int nt = 0; nt < 2; nt++)
            wmma::fill_fragment(acc[mt][nt], 0.0f);

    for (int k0 = 0; k0 < EMB; k0 += 16) {
        {
            const int ar = tid >> 2;
            const int ac = (tid & 3) * 4;
            #pragma unroll
            for (int p = 0; p < 2; p++) {
                const int r = ar + p * 64;
                float4 v = *(const float4*)&A[(size_t)(m0 + r) * EMB + k0 + ac];
                float h0 = to_tf32(v.x), h1 = to_tf32(v.y), h2 = to_tf32(v.z), h3 = to_tf32(v.w);
                AsH[r][ac + 0] = h0; AsL[r][ac + 0] = to_tf32(v.x - h0);
                AsH[r][ac + 1] = h1; AsL[r][ac + 1] = to_tf32(v.y - h1);
                AsH[r][ac + 2] = h2; AsL[r][ac + 2] = to_tf32(v.z - h2);
                AsH[r][ac + 3] = h3; AsL[r][ac + 3] = to_tf32(v.w - h3);
            }
        }
        {
            const int br = tid >> 5;
            const int bc = (tid & 31) * 4;
            #pragma unroll
            for (int p = 0; p < 2; p++) {
                const int r = br + p * 8;
                float4 v = *(const float4*)&B[(size_t)(k0 + r) * Ndim + n0 + bc];
                float h0 = to_tf32(v.x), h1 = to_tf32(v.y), h2 = to_tf32(v.z), h3 = to_tf32(v.w);
                BsH[r][bc + 0] = h0; BsL[r][bc + 0] = to_tf32(v.x - h0);
                BsH[r][bc + 1] = h1; BsL[r][bc + 1] = to_tf32(v.y - h1);
                BsH[r][bc + 2] = h2; BsL[r][bc + 2] = to_tf32(v.z - h2);
                BsH[r][bc + 3] = h3; BsL[r][bc + 3] = to_tf32(v.w - h3);
            }
        }
        __syncthreads();

        #pragma unroll
        for (int ks = 0; ks < 2; ks++) {
            wmma::fragment<wmma::matrix_a, 16, 16, 8, wmma::precision::tf32, wmma::row_major> afH[4], afL[4];
            wmma::fragment<wmma::matrix_b, 16, 16, 8, wmma::precision::tf32, wmma::row_major> bfH[2], bfL[2];
            #pragma unroll
            for (int mt = 0; mt < 4; mt++) {
                wmma::load_matrix_sync(afH[mt], &AsH[warp_m * 64 + mt * 16][ks * 8], 24);
                wmma::load_matrix_sync(afL[mt], &AsL[warp_m * 64 + mt * 16][ks * 8], 24);
            }
            #pragma unroll
            for (int nt = 0; nt < 2; nt++) {
                wmma::load_matrix_sync(bfH[nt], &BsH[ks * 8][warp_n * 32 + nt * 16], 136);
                wmma::load_matrix_sync(bfL[nt], &BsL[ks * 8][warp_n * 32 + nt * 16], 136);
            }
            #pragma unroll
            for (int mt = 0; mt < 4; mt++)
                #pragma unroll
                for (int nt = 0; nt < 2; nt++) {
                    wmma::mma_sync(acc[mt][nt], afL[mt], bfH[nt], acc[mt][nt]);
                    wmma::mma_sync(acc[mt][nt], afH[mt], bfL[nt], acc[mt][nt]);
                    wmma::mma_sync(acc[mt][nt], afH[mt], bfH[nt], acc[mt][nt]);
                }
        }
        __syncthreads();
    }

    #pragma unroll
    for (int mt = 0; mt < 4; mt++)
        #pragma unroll
        for (int nt = 0; nt < 2; nt++)
            wmma::store_matrix_sync(
                &C[(size_t)(m0 + warp_m * 64 + mt * 16) * Ndim + n0 + warp_n * 32 + nt * 16],
                acc[mt][nt], Ndim, wmma::mem_row_major);
}

// ---------------------------------------------------------------------------
// RoPE: in-place on g_qkv q,k columns (0..2047).
// ---------------------------------------------------------------------------
__global__ __launch_bounds__(256) void rope_kernel(const float* __restrict__ freqs)
{
    const int idx = blockIdx.x * 256 + threadIdx.x;
    const int row = idx >> 9;
    const int col = (idx & 511) * 4;
    float* p = &g_qkv[(size_t)row * QKVN + col];
    float4 v = *(float4*)p;
    const int l = row & (SEQ - 1);
    const int d0 = col & (HD - 1);
    const float* f = &freqs[(size_t)l * HD + d0];
    float f0 = f[0], f1 = f[1], f2 = f[2], f3 = f[3];
    float4 o;
    o.x = v.x * f0 - v.y * f1;
    o.y = v.y * f0 + v.x * f1;
    o.z = v.z * f2 - v.w * f3;
    o.w = v.w * f2 + v.z * f3;
    *(float4*)p = o;
}

// ---------------------------------------------------------------------------
// Flash attention, register-resident mma.sync m16n8k8 tf32.
// Block: 64 q-rows, one (b,h). 128 threads = 4 warps; warp owns 16 q-rows.
// S = Q@K^T in 3xTF32 (accuracy-critical: feeds exp); PV single tf32.
// S/P/O all live in registers; only K/V tiles in smem (52KB).
// mma.m16n8k8 fragment maps (g=lane>>2, t=lane&3):
//   A: a0=(g,t) a1=(g+8,t) a2=(g,t+4) a3=(g+8,t+4)
//   B: b0=(k=t,n=g) b1=(k=t+4,n=g)
//   C: c0=(g,2t) c1=(g,2t+1) c2=(g+8,2t) c3=(g+8,2t+1)
// ---------------------------------------------------------------------------
#define KLD 68
__global__ __launch_bounds__(128) void attn_kernel(const float* __restrict__ bias)
{
    extern __shared__ float sm[];
    float* Ksh = sm;                 // 64 x KLD (K hi)
    float* Ksl = sm + 64 * KLD;      // 64 x KLD (K lo)
    float* Vs  = sm + 2 * 64 * KLD;  // 64 x KLD (V tf32)

    const int tid  = threadIdx.x;
    const int lane = tid & 31;
    const int w    = tid >> 5;       // warp 0..3
    const int g    = lane >> 2;      // group row
    const int tg   = lane & 3;       // thread in group
    const int q0   = blockIdx.x * 64;
    const int h    = blockIdx.y;
    const int b    = blockIdx.z;

    const int rowA = q0 + w * 16 + g;      // local q rows rowA, rowA+8
    const float scale = 0.125f;            // 1/sqrt(64)

    // --- Q fragments (hi/lo split), resident for whole kernel -------------
    uint32_t qh[8][4], ql[8][4];
    {
        const float* qA = &g_qkv[(size_t)(b * SEQ + rowA) * QKVN + h * HD];
        const float* qB = qA + (size_t)8 * QKVN;   // row rowA+8
        #pragma unroll
        for (int ks = 0; ks < 8; ks++) {
            float v0 = qA[ks * 8 + tg]     * scale;
            float v1 = qB[ks * 8 + tg]     * scale;
            float v2 = qA[ks * 8 + tg + 4] * scale;
            float v3 = qB[ks * 8 + tg + 4] * scale;
            float h0 = to_tf32(v0), h1 = to_tf32(v1), h2 = to_tf32(v2), h3 = to_tf32(v3);
            qh[ks][0] = __float_as_uint(h0); ql[ks][0] = __float_as_uint(to_tf32(v0 - h0));
            qh[ks][1] = __float_as_uint(h1); ql[ks][1] = __float_as_uint(to_tf32(v1 - h1));
            qh[ks][2] = __float_as_uint(h2); ql[ks][2] = __float_as_uint(to_tf32(v2 - h2));
            qh[ks][3] = __float_as_uint(h3); ql[ks][3] = __float_as_uint(to_tf32(v3 - h3));
        }
    }

    float o[8][4];
    #pragma unroll
    for (int nb = 0; nb < 8; nb++)
        #pragma unroll
        for (int j = 0; j < 4; j++) o[nb][j] = 0.0f;
    float m0 = -1e30f, m1 = -1e30f, l0 = 0.0f, l1 = 0.0f;

    const int srcA = (lane & 28) | (tg >> 1);   // quad shuffle sources for P->A permute
    const int srcB = srcA + 2;
    const bool odd = (tg & 1);

    for (int kt = 0; kt < SEQ / 64; kt++) {
        __syncthreads();   // prior-iter smem reads complete
        // --- cooperative K/V tile load (64 keys x 64 d) --------------------
        #pragma unroll
        for (int i = 0; i < 8; i++) {
            const int f = tid + i * 128;        // 0..1023 float4 ids
            const int r = f >> 4;
            const int c = (f & 15) * 4;
            const size_t gb = (size_t)(b * SEQ + kt * 64 + r) * QKVN + h * HD + c;
            float4 kv = *(const float4*)&g_qkv[gb + EMB];
            float h0 = to_tf32(kv.x), h1 = to_tf32(kv.y), h2 = to_tf32(kv.z), h3 = to_tf32(kv.w);
            Ksh[r * KLD + c + 0] = h0; Ksl[r * KLD + c + 0] = to_tf32(kv.x - h0);
            Ksh[r * KLD + c + 1] = h1; Ksl[r * KLD + c + 1] = to_tf32(kv.y - h1);
            Ksh[r * KLD + c + 2] = h2; Ksl[r * KLD + c + 2] = to_tf32(kv.z - h2);
            Ksh[r * KLD + c + 3] = h3; Ksl[r * KLD + c + 3] = to_tf32(kv.w - h3);
            float4 vv = *(const float4*)&g_qkv[gb + 2 * EMB];
            Vs[r * KLD + c + 0] = to_tf32(vv.x);
            Vs[r * KLD + c + 1] = to_tf32(vv.y);
            Vs[r * KLD + c + 2] = to_tf32(vv.z);
            Vs[r * KLD + c + 3] = to_tf32(vv.w);
        }
        __syncthreads();

        // --- S = Q @ K^T (3xTF32) ------------------------------------------
        float s[8][4];
        #pragma unroll
        for (int nb = 0; nb < 8; nb++)
            #pragma unroll
            for (int j = 0; j < 4; j++) s[nb][j] = 0.0f;

        #pragma unroll
        for (int ks = 0; ks < 8; ks++) {
            #pragma unroll
            for (int nb = 0; nb < 8; nb++) {
                const int krow = nb * 8 + g;
                uint32_t bh[2], bl[2];
                bh[0] = __float_as_uint(Ksh[krow * KLD + ks * 8 + tg]);
                bh[1] = __float_as_uint(Ksh[krow * KLD + ks * 8 + tg + 4]);
                bl[0] = __float_as_uint(Ksl[krow * KLD + ks * 8 + tg]);
                bl[1] = __float_as_uint(Ksl[krow * KLD + ks * 8 + tg + 4]);
                mma_16n8k8(s[nb], ql[ks], bh);
                mma_16n8k8(s[nb], qh[ks], bl);
                mma_16n8k8(s[nb], qh[ks], bh);
            }
        }

        // --- bias + online softmax on register fragments --------------------
        const float* bp = &bias[((size_t)h * SEQ + rowA) * SEQ + kt * 64];
        float mx0 = -1e30f, mx1 = -1e30f;
        #pragma unroll
        for (int nb = 0; nb < 8; nb++) {
            float2 b0 = __ldcs((const float2*)(bp + nb * 8 + 2 * tg));
            float2 b1 = __ldcs((const float2*)(bp + (size_t)8 * SEQ + nb * 8 + 2 * tg));
            s[nb][0] += b0.x; s[nb][1] += b0.y;
            s[nb][2] += b1.x; s[nb][3] += b1.y;
            mx0 = fmaxf(mx0, fmaxf(s[nb][0], s[nb][1]));
            mx1 = fmaxf(mx1, fmaxf(s[nb][2], s[nb][3]));
        }
        mx0 = fmaxf(mx0, __shfl_xor_sync(0xffffffffu, mx0, 1));
        mx0 = fmaxf(mx0, __shfl_xor_sync(0xffffffffu, mx0, 2));
        mx1 = fmaxf(mx1, __shfl_xor_sync(0xffffffffu, mx1, 1));
        mx1 = fmaxf(mx1, __shfl_xor_sync(0xffffffffu, mx1, 2));
        const float nm0 = fmaxf(m0, mx0), nm1 = fmaxf(m1, mx1);
        const float al0 = __expf(m0 - nm0), al1 = __expf(m1 - nm1);
        m0 = nm0; m1 = nm1;

        float ts0 = 0.0f, ts1 = 0.0f;
        #pragma unroll
        for (int nb = 0; nb < 8; nb++) {
            float e0 = __expf(s[nb][0] - nm0);
            float e1 = __expf(s[nb][1] - nm0);
            float e2 = __expf(s[nb][2] - nm1);
            float e3 = __expf(s[nb][3] - nm1);
            ts0 += e0 + e1; ts1 += e2 + e3;
            s[nb][0] = to_tf32(e0); s[nb][1] = to_tf32(e1);
            s[nb][2] = to_tf32(e2); s[nb][3] = to_tf32(e3);
        }
        ts0 += __shfl_xor_sync(0xffffffffu, ts0, 1);
        ts0 += __shfl_xor_sync(0xffffffffu, ts0, 2);
        ts1 += __shfl_xor_sync(0xffffffffu, ts1, 1);
        ts1 += __shfl_xor_sync(0xffffffffu, ts1, 2);
        l0 = l0 * al0 + ts0;
        l1 = l1 * al1 + ts1;
        #pragma unroll
        for (int nb = 0; nb < 8; nb++) {
            o[nb][0] *= al0; o[nb][1] *= al0;
            o[nb][2] *= al1; o[nb][3] *= al1;
        }

        // --- O += P @ V ; P permuted C-layout -> A-layout via quad shuffles --
        #pragma unroll
        for (int ks = 0; ks < 8; ks++) {
            float e0 = __shfl_sync(0xffffffffu, s[ks][0], srcA);
            float e1 = __shfl_sync(0xffffffffu, s[ks][1], srcA);
            float e2 = __shfl_sync(0xffffffffu, s[ks][2], srcA);
            float e3 = __shfl_sync(0xffffffffu, s[ks][3], srcA);
            float f0 = __shfl_sync(0xffffffffu, s[ks][0], srcB);
            float f1 = __shfl_sync(0xffffffffu, s[ks][1], srcB);
            float f2 = __shfl_sync(0xffffffffu, s[ks][2], srcB);
            float f3 = __shfl_sync(0xffffffffu, s[ks][3], srcB);
            uint32_t a[4];
            a[0] = __float_as_uint(odd ? e1 : e0);
            a[1] = __float_as_uint(odd ? e3 : e2);
            a[2] = __float_as_uint(odd ? f1 : f0);
            a[3] = __float_as_uint(odd ? f3 : f2);
            #pragma unroll
            for (int nb = 0; nb < 8; nb++) {
                uint32_t vb[2];
                vb[0] = __float_as_uint(Vs[(ks * 8 + tg)     * KLD + nb * 8 + g]);
                vb[1] = __float_as_uint(Vs[(ks * 8 + tg + 4) * KLD + nb * 8 + g]);
                mma_16n8k8(o[nb], a, vb);
            }
        }
    }

    // --- epilogue: normalize, write ----------------------------------------
    const float inv0 = 1.0f / l0, inv1 = 1.0f / l1;
    float* oA = &g_attn[(size_t)(b * SEQ + rowA) * EMB + h * HD];
    float* oB = oA + (size_t)8 * EMB;
    #pragma unroll
    for (int nb = 0; nb < 8; nb++) {
        *(float2*)(oA + nb * 8 + 2 * tg) = make_float2(o[nb][0] * inv0, o[nb][1] * inv0);
        *(float2*)(oB + nb * 8 + 2 * tg) = make_float2(o[nb][2] * inv1, o[nb][3] * inv1);
    }
}

// ---------------------------------------------------------------------------
// Proj bias add: out[row][col] += b_proj[col]
// ---------------------------------------------------------------------------
__global__ __launch_bounds__(256) void bias_add(float* __restrict__ out,
                                                const float* __restrict__ bproj)
{
    const int idx = blockIdx.x * 256 + threadIdx.x;
    const int c4 = (idx & 255) * 4;
    float4 v = *(float4*)&out[(size_t)idx * 4];
    const float4 bp = *(const float4*)&bproj[c4];
    v.x += bp.x; v.y += bp.y; v.z += bp.z; v.w += bp.w;
    *(float4*)&out[(size_t)idx * 4] = v;
}

// ---------------------------------------------------------------------------
extern "C" void kernel_launch(void* const* d_in, const int* in_sizes, int n_in,
                              void* d_out, int out_size)
{
    const float* x      = (const float*)d_in[0];  // (2,2048,1024)
    const float* freqs  = (const float*)d_in[1];  // (2048,32,2)
    const float* bias   = (const float*)d_in[2];  // (1,16,2048,2048)
    const float* w_qkv  = (const float*)d_in[3];  // (1024,3072)
    const float* w_proj = (const float*)d_in[4];  // (1024,1024)
    const float* b_proj = (const float*)d_in[5];  // (1024,)
    float* out = (float*)d_out;                   // (2,2048,1024)

    float* qkv_ptr;  cudaGetSymbolAddress((void**)&qkv_ptr, g_qkv);
    float* attn_ptr; cudaGetSymbolAddress((void**)&attn_ptr, g_attn);

    const int attn_smem = 3 * 64 * KLD * sizeof(float);  // 52224 B
    cudaFuncSetAttribute(attn_kernel, cudaFuncAttributeMaxDynamicSharedMemorySize, attn_smem);

    // 1) QKV GEMM (3xTF32, near-fp32) -> g_qkv
    gemm_3xtf32<<<dim3(QKVN / 128, MROWS / 128), 256>>>(x, w_qkv, qkv_ptr, QKVN);
    // 2) RoPE in place on q,k
    rope_kernel<<<(MROWS * 2048 / 4) / 256, 256>>>(freqs);
    // 3) attention -> g_attn
    attn_kernel<<<dim3(SEQ / 64, HEADS, BATCH), 128, attn_smem>>>(bias);
    // 4) proj GEMM (3xTF32) -> out
    gemm_3xtf32<<<dim3(EMB / 128, MROWS / 128), 256>>>(attn_ptr, w_proj, out, EMB);
    // 5) + b_proj
    bias_add<<<(MROWS * EMB / 4) / 256, 256>>>(out, b_proj);
}

// round 6
// speedup vs baseline: 1.3661x; 1.1027x over previous
#include <cuda_runtime.h>
#include <cuda_bf16.h>
#include <mma.h>
#include <cstdint>

using namespace nvcuda;

#define BATCH 2
#define SEQ   2048
#define HEADS 16
#define HD    64
#define EMB   1024
#define MROWS (BATCH*SEQ)
#define QKVN  (3*EMB)

__device__ float g_qkv[(size_t)MROWS * QKVN];
__device__ float g_attn[(size_t)MROWS * EMB];

__device__ __forceinline__ float to_tf32(float x) {
    float y;
    asm("cvt.rna.tf32.f32 %0, %1;" : "=f"(y) : "f"(x));
    return y;
}
__device__ __forceinline__ uint32_t pack_bf16x2(float e0, float e1) {
    uint32_t r;
    asm("cvt.rn.bf16x2.f32 %0, %1, %2;" : "=r"(r) : "f"(e1), "f"(e0));
    return r;
}
__device__ __forceinline__ void split2(float x, float y, uint32_t& hp, uint32_t& lp) {
    float hx = __bfloat162float(__float2bfloat16_rn(x));
    float hy = __bfloat162float(__float2bfloat16_rn(y));
    hp = pack_bf16x2(hx, hy);
    lp = pack_bf16x2(x - hx, y - hy);
}
__device__ __forceinline__ void mma_bf16(float c[4], const uint32_t a[4], const uint32_t b[2]) {
    asm volatile(
        "mma.sync.aligned.m16n8k16.row.col.f32.bf16.bf16.f32 "
        "{%0,%1,%2,%3}, {%4,%5,%6,%7}, {%8,%9}, {%0,%1,%2,%3};"
        : "+f"(c[0]), "+f"(c[1]), "+f"(c[2]), "+f"(c[3])
        : "r"(a[0]), "r"(a[1]), "r"(a[2]), "r"(a[3]), "r"(b[0]), "r"(b[1]));
}

// ---------------------------------------------------------------------------
// 3xTF32 GEMM (unchanged)
// ---------------------------------------------------------------------------
__global__ __launch_bounds__(256) void gemm_3xtf32(
    const float* __restrict__ A, const float* __restrict__ B,
    float* __restrict__ C, int Ndim)
{
    __shared__ float AsH[128][24];
    __shared__ float AsL[128][24];
    __shared__ float BsH[16][136];
    __shared__ float BsL[16][136];

    const int tid = threadIdx.x;
    const int warp = tid >> 5;
    const int warp_m = warp >> 2;
    const int warp_n = warp & 3;
    const int m0 = blockIdx.y * 128;
    const int n0 = blockIdx.x * 128;

    wmma::fragment<wmma::accumulator, 16, 16, 8, float> acc[4][2];
    #pragma unroll
    for (int mt = 0; mt < 4; mt++)
        #pragma unroll
        for (int nt = 0; nt < 2; nt++)
            wmma::fill_fragment(acc[mt][nt], 0.0f);

    for (int k0 = 0; k0 < EMB; k0 += 16) {
        {
            const int ar = tid >> 2;
            const int ac = (tid & 3) * 4;
            #pragma unroll
            for (int p = 0; p < 2; p++) {
                const int r = ar + p * 64;
                float4 v = *(const float4*)&A[(size_t)(m0 + r) * EMB + k0 + ac];
                float h0 = to_tf32(v.x), h1 = to_tf32(v.y), h2 = to_tf32(v.z), h3 = to_tf32(v.w);
                AsH[r][ac + 0] = h0; AsL[r][ac + 0] = to_tf32(v.x - h0);
                AsH[r][ac + 1] = h1; AsL[r][ac + 1] = to_tf32(v.y - h1);
                AsH[r][ac + 2] = h2; AsL[r][ac + 2] = to_tf32(v.z - h2);
                AsH[r][ac + 3] = h3; AsL[r][ac + 3] = to_tf32(v.w - h3);
            }
        }
        {
            const int br = tid >> 5;
            const int bc = (tid & 31) * 4;
            #pragma unroll
            for (int p = 0; p < 2; p++) {
                const int r = br + p * 8;
                float4 v = *(const float4*)&B[(size_t)(k0 + r) * Ndim + n0 + bc];
                float h0 = to_tf32(v.x), h1 = to_tf32(v.y), h2 = to_tf32(v.z), h3 = to_tf32(v.w);
                BsH[r][bc + 0] = h0; BsL[r][bc + 0] = to_tf32(v.x - h0);
                BsH[r][bc + 1] = h1; BsL[r][bc + 1] = to_tf32(v.y - h1);
                BsH[r][bc + 2] = h2; BsL[r][bc + 2] = to_tf32(v.z - h2);
                BsH[r][bc + 3] = h3; BsL[r][bc + 3] = to_tf32(v.w - h3);
            }
        }
        __syncthreads();

        #pragma unroll
        for (int ks = 0; ks < 2; ks++) {
            wmma::fragment<wmma::matrix_a, 16, 16, 8, wmma::precision::tf32, wmma::row_major> afH[4], afL[4];
            wmma::fragment<wmma::matrix_b, 16, 16, 8, wmma::precision::tf32, wmma::row_major> bfH[2], bfL[2];
            #pragma unroll
            for (int mt = 0; mt < 4; mt++) {
                wmma::load_matrix_sync(afH[mt], &AsH[warp_m * 64 + mt * 16][ks * 8], 24);
                wmma::load_matrix_sync(afL[mt], &AsL[warp_m * 64 + mt * 16][ks * 8], 24);
            }
            #pragma unroll
            for (int nt = 0; nt < 2; nt++) {
                wmma::load_matrix_sync(bfH[nt], &BsH[ks * 8][warp_n * 32 + nt * 16], 136);
                wmma::load_matrix_sync(bfL[nt], &BsL[ks * 8][warp_n * 32 + nt * 16], 136);
            }
            #pragma unroll
            for (int mt = 0; mt < 4; mt++)
                #pragma unroll
                for (int nt = 0; nt < 2; nt++) {
                    wmma::mma_sync(acc[mt][nt], afL[mt], bfH[nt], acc[mt][nt]);
                    wmma::mma_sync(acc[mt][nt], afH[mt], bfL[nt], acc[mt][nt]);
                    wmma::mma_sync(acc[mt][nt], afH[mt], bfH[nt], acc[mt][nt]);
                }
        }
        __syncthreads();
    }

    #pragma unroll
    for (int mt = 0; mt < 4; mt++)
        #pragma unroll
        for (int nt = 0; nt < 2; nt++)
            wmma::store_matrix_sync(
                &C[(size_t)(m0 + warp_m * 64 + mt * 16) * Ndim + n0 + warp_n * 32 + nt * 16],
                acc[mt][nt], Ndim, wmma::mem_row_major);
}

__global__ __launch_bounds__(256) void rope_kernel(const float* __restrict__ freqs)
{
    const int idx = blockIdx.x * 256 + threadIdx.x;
    const int row = idx >> 9;
    const int col = (idx & 511) * 4;
    float* p = &g_qkv[(size_t)row * QKVN + col];
    float4 v = *(float4*)p;
    const int l = row & (SEQ - 1);
    const int d0 = col & (HD - 1);
    const float* f = &freqs[(size_t)l * HD + d0];
    float f0 = f[0], f1 = f[1], f2 = f[2], f3 = f[3];
    float4 o;
    o.x = v.x * f0 - v.y * f1;
    o.y = v.y * f0 + v.x * f1;
    o.z = v.z * f2 - v.w * f3;
    o.w = v.w * f2 + v.z * f3;
    *(float4*)p = o;
}

// ---------------------------------------------------------------------------
// Flash attention, 3xBF16 hi/lo-split mma.sync m16n8k16 (see header comment
// in theory above for fragment/layout derivation).
// ---------------------------------------------------------------------------
#define LT 72
__global__ __launch_bounds__(128) void attn_kernel(const float* __restrict__ bias)
{
    __shared__ uint32_t KsTh[32][LT];
    __shared__ uint32_t KsTl[32][LT];
    __shared__ uint32_t VtPh[32][LT];
    __shared__ uint32_t VtPl[32][LT];

    const int tid  = threadIdx.x;
    const int lane = tid & 31;
    const int w    = tid >> 5;
    const int g    = lane >> 2;
    const int tg   = lane & 3;
    const int q0   = blockIdx.x * 64;
    const int h    = blockIdx.y;
    const int b    = blockIdx.z;

    const int rowA = q0 + w * 16 + g;
    const float scale = 0.125f;

    uint32_t qh[4][4], ql[4][4];
    {
        const float* qA = &g_qkv[(size_t)(b * SEQ + rowA) * QKVN + h * HD];
        const float* qB = qA + (size_t)8 * QKVN;
        #pragma unroll
        for (int ks = 0; ks < 4; ks++) {
            const int d0 = ks * 16 + 2 * tg;
            float2 x0 = *(const float2*)&qA[d0];
            float2 x1 = *(const float2*)&qB[d0];
            float2 x2 = *(const float2*)&qA[d0 + 8];
            float2 x3 = *(const float2*)&qB[d0 + 8];
            split2(x0.x * scale, x0.y * scale, qh[ks][0], ql[ks][0]);
            split2(x1.x * scale, x1.y * scale, qh[ks][1], ql[ks][1]);
            split2(x2.x * scale, x2.y * scale, qh[ks][2], ql[ks][2]);
            split2(x3.x * scale, x3.y * scale, qh[ks][3], ql[ks][3]);
        }
    }

    float o[8][4];
    #pragma unroll
    for (int nb = 0; nb < 8; nb++)
        #pragma unroll
        for (int j = 0; j < 4; j++) o[nb][j] = 0.0f;
    float m0 = -1e30f, m1 = -1e30f, l0 = 0.0f, l1 = 0.0f;

    const int u  = tid & 31;
    const int cq = tid >> 5;

    for (int kt = 0; kt < SEQ / 64; kt++) {
        __syncthreads();
        #pragma unroll
        for (int i = 0; i < 4; i++) {
            const int c = cq * 4 + i * 16;
            const size_t base = (size_t)(b * SEQ + kt * 64 + 2 * u) * QKVN + h * HD + c;
            float4 k0 = *(const float4*)&g_qkv[base + EMB];
            float4 k1 = *(const float4*)&g_qkv[base + EMB + QKVN];
            float4 v0 = *(const float4*)&g_qkv[base + 2 * EMB];
            float4 v1 = *(const float4*)&g_qkv[base + 2 * EMB + QKVN];
            uint32_t ha, la, hb, lb;
            split2(k0.x, k0.y, ha, la);
            split2(k1.x, k1.y, hb, lb);
            *(uint2*)&KsTh[c / 2][2 * u] = make_uint2(ha, hb);
            *(uint2*)&KsTl[c / 2][2 * u] = make_uint2(la, lb);
            split2(k0.z, k0.w, ha, la);
            split2(k1.z, k1.w, hb, lb);
            *(uint2*)&KsTh[c / 2 + 1][2 * u] = make_uint2(ha, hb);
            *(uint2*)&KsTl[c / 2 + 1][2 * u] = make_uint2(la, lb);
            uint32_t vh[4], vl[4];
            split2(v0.x, v1.x, vh[0], vl[0]);
            split2(v0.y, v1.y, vh[1], vl[1]);
            split2(v0.z, v1.z, vh[2], vl[2]);
            split2(v0.w, v1.w, vh[3], vl[3]);
            *(uint4*)&VtPh[u][c] = make_uint4(vh[0], vh[1], vh[2], vh[3]);
            *(uint4*)&VtPl[u][c] = make_uint4(vl[0], vl[1], vl[2], vl[3]);
        }
        __syncthreads();

        float s[8][4];
        #pragma unroll
        for (int nb = 0; nb < 8; nb++)
            #pragma unroll
            for (int j = 0; j < 4; j++) s[nb][j] = 0.0f;

        #pragma unroll
        for (int ks = 0; ks < 4; ks++) {
            #pragma unroll
            for (int nb = 0; nb < 8; nb++) {
                uint32_t bh[2], bl[2];
                bh[0] = KsTh[8 * ks + tg][8 * nb + g];
                bh[1] = KsTh[8 * ks + tg + 4][8 * nb + g];
                bl[0] = KsTl[8 * ks + tg][8 * nb + g];
                bl[1] = KsTl[8 * ks + tg + 4][8 * nb + g];
                mma_bf16(s[nb], ql[ks], bh);
                mma_bf16(s[nb], qh[ks], bl);
                mma_bf16(s[nb], qh[ks], bh);
            }
        }

        const float* bp = &bias[((size_t)h * SEQ + rowA) * SEQ + kt * 64];
        float mx0 = -1e30f, mx1 = -1e30f;
        #pragma unroll
        for (int nb = 0; nb < 8; nb++) {
            float2 b0 = __ldcs((const float2*)(bp + nb * 8 + 2 * tg));
            float2 b1 = __ldcs((const float2*)(bp + (size_t)8 * SEQ + nb * 8 + 2 * tg));
            s[nb][0] += b0.x; s[nb][1] += b0.y;
            s[nb][2] += b1.x; s[nb][3] += b1.y;
            mx0 = fmaxf(mx0, fmaxf(s[nb][0], s[nb][1]));
            mx1 = fmaxf(mx1, fmaxf(s[nb][2], s[nb][3]));
        }
        mx0 = fmaxf(mx0, __shfl_xor_sync(0xffffffffu, mx0, 1));
        mx0 = fmaxf(mx0, __shfl_xor_sync(0xffffffffu, mx0, 2));
        mx1 = fmaxf(mx1, __shfl_xor_sync(0xffffffffu, mx1, 1));
        mx1 = fmaxf(mx1, __shfl_xor_sync(0xffffffffu, mx1, 2));
        const float nm0 = fmaxf(m0, mx0), nm1 = fmaxf(m1, mx1);
        const float al0 = __expf(m0 - nm0), al1 = __expf(m1 - nm1);
        m0 = nm0; m1 = nm1;

        float ts0 = 0.0f, ts1 = 0.0f;
        #pragma unroll
        for (int nb = 0; nb < 8; nb++) {
            s[nb][0] = __expf(s[nb][0] - nm0);
            s[nb][1] = __expf(s[nb][1] - nm0);
            s[nb][2] = __expf(s[nb][2] - nm1);
            s[nb][3] = __expf(s[nb][3] - nm1);
            ts0 += s[nb][0] + s[nb][1];
            ts1 += s[nb][2] + s[nb][3];
        }
        ts0 += __shfl_xor_sync(0xffffffffu, ts0, 1);
        ts0 += __shfl_xor_sync(0xffffffffu, ts0, 2);
        ts1 += __shfl_xor_sync(0xffffffffu, ts1, 1);
        ts1 += __shfl_xor_sync(0xffffffffu, ts1, 2);
        l0 = l0 * al0 + ts0;
        l1 = l1 * al1 + ts1;
        #pragma unroll
        for (int nb = 0; nb < 8; nb++) {
            o[nb][0] *= al0; o[nb][1] *= al0;
            o[nb][2] *= al1; o[nb][3] *= al1;
        }

        #pragma unroll
        for (int j = 0; j < 4; j++) {
            uint32_t ah[4], al_[4];
            split2(s[2 * j][0],     s[2 * j][1],     ah[0], al_[0]);
            split2(s[2 * j][2],     s[2 * j][3],     ah[1], al_[1]);
            split2(s[2 * j + 1][0], s[2 * j + 1][1], ah[2], al_[2]);
            split2(s[2 * j + 1][2], s[2 * j + 1][3], ah[3], al_[3]);
            #pragma unroll
            for (int nb = 0; nb < 8; nb++) {
                uint32_t vh[2], vl[2];
                vh[0] = VtPh[8 * j + tg][8 * nb + g];
                vh[1] = VtPh[8 * j + tg + 4][8 * nb + g];
                vl[0] = VtPl[8 * j + tg][8 * nb + g];
                vl[1] = VtPl[8 * j + tg + 4][8 * nb + g];
                mma_bf16(o[nb], al_, vh);
                mma_bf16(o[nb], ah,  vl);
                mma_bf16(o[nb], ah,  vh);
            }
        }
    }

    const float inv0 = 1.0f / l0, inv1 = 1.0f / l1;
    float* oA = &g_attn[(size_t)(b * SEQ + rowA) * EMB + h * HD];
    float* oB = oA + (size_t)8 * EMB;
    #pragma unroll
    for (int nb = 0; nb < 8; nb++) {
        *(float2*)(oA + nb * 8 + 2 * tg) = make_float2(o[nb][0] * inv0, o[nb][1] * inv0);
        *(float2*)(oB + nb * 8 + 2 * tg) = make_float2(o[nb][2] * inv1, o[nb][3] * inv1);
    }
}

__global__ __launch_bounds__(256) void bias_add(float* __restrict__ out,
                                                const float* __restrict__ bproj)
{
    const int idx = blockIdx.x * 256 + threadIdx.x;
    const int c4 = (idx & 255) * 4;
    float4 v = *(float4*)&out[(size_t)idx * 4];
    const float4 bp = *(const float4*)&bproj[c4];
    v.x += bp.x; v.y += bp.y; v.z += bp.z; v.w += bp.w;
    *(float4*)&out[(size_t)idx * 4] = v;
}

extern "C" void kernel_launch(void* const* d_in, const int* in_sizes, int n_in,
                              void* d_out, int out_size)
{
    const float* x      = (const float*)d_in[0];
    const float* freqs  = (const float*)d_in[1];
    const float* bias   = (const float*)d_in[2];
    const float* w_qkv  = (const float*)d_in[3];
    const float* w_proj = (const float*)d_in[4];
    const float* b_proj = (const float*)d_in[5];
    float* out = (float*)d_out;

    float* qkv_ptr;  cudaGetSymbolAddress((void**)&qkv_ptr, g_qkv);
    float* attn_ptr; cudaGetSymbolAddress((void**)&attn_ptr, g_attn);

    gemm_3xtf32<<<dim3(QKVN / 128, MROWS / 128), 256>>>(x, w_qkv, qkv_ptr, QKVN);
    rope_kernel<<<(MROWS * 2048 / 4) / 256, 256>>>(freqs);
    attn_kernel<<<dim3(SEQ / 64, HEADS, BATCH), 128>>>(bias);
    gemm_3xtf32<<<dim3(EMB / 128, MROWS / 128), 256>>>(attn_ptr, w_proj, out, EMB);
    bias_add<<<(MROWS * EMB / 4) / 256, 256>>>(out, b_proj);
}

// round 7
// speedup vs baseline: 1.4668x; 1.0737x over previous
#include <cuda_runtime.h>
#include <cuda_bf16.h>
#include <mma.h>
#include <cstdint>

using namespace nvcuda;

#define BATCH 2
#define SEQ   2048
#define HEADS 16
#define HD    64
#define EMB   1024
#define MROWS (BATCH*SEQ)
#define QKVN  (3*EMB)
#define NKT   (SEQ/64)           // 32 key tiles

__device__ float g_qkv[(size_t)MROWS * QKVN];   // 50.3 MB
__device__ float g_attn[(size_t)MROWS * EMB];   // 16.8 MB
// Pre-split K/V tiles: [b*H+h][kt][4 arrays: Kh,Kl,Vh,Vl][32 rows][64 cols] u32
__device__ uint32_t g_kvsp[(size_t)BATCH * HEADS * NKT * 4 * 32 * 64];  // 67.1 MB
__device__ int g_dummy;

__device__ __forceinline__ float to_tf32(float x) {
    float y;
    asm("cvt.rna.tf32.f32 %0, %1;" : "=f"(y) : "f"(x));
    return y;
}
__device__ __forceinline__ uint32_t pack_bf16x2(float e0, float e1) {
    uint32_t r;
    asm("cvt.rn.bf16x2.f32 %0, %1, %2;" : "=r"(r) : "f"(e1), "f"(e0));
    return r;
}
__device__ __forceinline__ void split2(float x, float y, uint32_t& hp, uint32_t& lp) {
    float hx = __bfloat162float(__float2bfloat16_rn(x));
    float hy = __bfloat162float(__float2bfloat16_rn(y));
    hp = pack_bf16x2(hx, hy);
    lp = pack_bf16x2(x - hx, y - hy);
}
__device__ __forceinline__ void mma_bf16(float c[4], const uint32_t a[4], const uint32_t b[2]) {
    asm volatile(
        "mma.sync.aligned.m16n8k16.row.col.f32.bf16.bf16.f32 "
        "{%0,%1,%2,%3}, {%4,%5,%6,%7}, {%8,%9}, {%0,%1,%2,%3};"
        : "+f"(c[0]), "+f"(c[1]), "+f"(c[2]), "+f"(c[3])
        : "r"(a[0]), "r"(a[1]), "r"(a[2]), "r"(a[3]), "r"(b[0]), "r"(b[1]));
}
__device__ __forceinline__ void cp16(uint32_t dst, const void* src) {
    asm volatile("cp.async.cg.shared.global [%0], [%1], 16;" :: "r"(dst), "l"(src));
}
__device__ __forceinline__ void cp_commit() {
    asm volatile("cp.async.commit_group;");
}

// ---------------------------------------------------------------------------
// 3xTF32 GEMM (unchanged; measured 369us QKV)
// ---------------------------------------------------------------------------
__global__ __launch_bounds__(256) void gemm_3xtf32(
    const float* __restrict__ A, const float* __restrict__ B,
    float* __restrict__ C, int Ndim)
{
    __shared__ float AsH[128][24];
    __shared__ float AsL[128][24];
    __shared__ float BsH[16][136];
    __shared__ float BsL[16][136];

    const int tid = threadIdx.x;
    const int warp = tid >> 5;
    const int warp_m = warp >> 2;
    const int warp_n = warp & 3;
    const int m0 = blockIdx.y * 128;
    const int n0 = blockIdx.x * 128;

    wmma::fragment<wmma::accumulator, 16, 16, 8, float> acc[4][2];
    #pragma unroll
    for (int mt = 0; mt < 4; mt++)
        #pragma unroll
        for (int nt = 0; nt < 2; nt++)
            wmma::fill_fragment(acc[mt][nt], 0.0f);

    for (int k0 = 0; k0 < EMB; k0 += 16) {
        {
            const int ar = tid >> 2;
            const int ac = (tid & 3) * 4;
            #pragma unroll
            for (int p = 0; p < 2; p++) {
                const int r = ar + p * 64;
                float4 v = *(const float4*)&A[(size_t)(m0 + r) * EMB + k0 + ac];
                float h0 = to_tf32(v.x), h1 = to_tf32(v.y), h2 = to_tf32(v.z), h3 = to_tf32(v.w);
                AsH[r][ac + 0] = h0; AsL[r][ac + 0] = to_tf32(v.x - h0);
                AsH[r][ac + 1] = h1; AsL[r][ac + 1] = to_tf32(v.y - h1);
                AsH[r][ac + 2] = h2; AsL[r][ac + 2] = to_tf32(v.z - h2);
                AsH[r][ac + 3] = h3; AsL[r][ac + 3] = to_tf32(v.w - h3);
            }
        }
        {
            const int br = tid >> 5;
            const int bc = (tid & 31) * 4;
            #pragma unroll
            for (int p = 0; p < 2; p++) {
                const int r = br + p * 8;
                float4 v = *(const float4*)&B[(size_t)(k0 + r) * Ndim + n0 + bc];
                float h0 = to_tf32(v.x), h1 = to_tf32(v.y), h2 = to_tf32(v.z), h3 = to_tf32(v.w);
                BsH[r][bc + 0] = h0; BsL[r][bc + 0] = to_tf32(v.x - h0);
                BsH[r][bc + 1] = h1; BsL[r][bc + 1] = to_tf32(v.y - h1);
                BsH[r][bc + 2] = h2; BsL[r][bc + 2] = to_tf32(v.z - h2);
                BsH[r][bc + 3] = h3; BsL[r][bc + 3] = to_tf32(v.w - h3);
            }
        }
        __syncthreads();

        #pragma unroll
        for (int ks = 0; ks < 2; ks++) {
            wmma::fragment<wmma::matrix_a, 16, 16, 8, wmma::precision::tf32, wmma::row_major> afH[4], afL[4];
            wmma::fragment<wmma::matrix_b, 16, 16, 8, wmma::precision::tf32, wmma::row_major> bfH[2], bfL[2];
            #pragma unroll
            for (int mt = 0; mt < 4; mt++) {
                wmma::load_matrix_sync(afH[mt], &AsH[warp_m * 64 + mt * 16][ks * 8], 24);
                wmma::load_matrix_sync(afL[mt], &AsL[warp_m * 64 + mt * 16][ks * 8], 24);
            }
            #pragma unroll
            for (int nt = 0; nt < 2; nt++) {
                wmma::load_matrix_sync(bfH[nt], &BsH[ks * 8][warp_n * 32 + nt * 16], 136);
                wmma::load_matrix_sync(bfL[nt], &BsL[ks * 8][warp_n * 32 + nt * 16], 136);
            }
            #pragma unroll
            for (int mt = 0; mt < 4; mt++)
                #pragma unroll
                for (int nt = 0; nt < 2; nt++) {
                    wmma::mma_sync(acc[mt][nt], afL[mt], bfH[nt], acc[mt][nt]);
                    wmma::mma_sync(acc[mt][nt], afH[mt], bfL[nt], acc[mt][nt]);
                    wmma::mma_sync(acc[mt][nt], afH[mt], bfH[nt], acc[mt][nt]);
                }
        }
        __syncthreads();
    }

    #pragma unroll
    for (int mt = 0; mt < 4; mt++)
        #pragma unroll
        for (int nt = 0; nt < 2; nt++)
            wmma::store_matrix_sync(
                &C[(size_t)(m0 + warp_m * 64 + mt * 16) * Ndim + n0 + warp_n * 32 + nt * 16],
                acc[mt][nt], Ndim, wmma::mem_row_major);
}

// ---------------------------------------------------------------------------
// RoPE in place on q,k
// ---------------------------------------------------------------------------
__global__ __launch_bounds__(256) void rope_kernel(const float* __restrict__ freqs)
{
    const int idx = blockIdx.x * 256 + threadIdx.x;
    const int row = idx >> 9;
    const int col = (idx & 511) * 4;
    float* p = &g_qkv[(size_t)row * QKVN + col];
    float4 v = *(float4*)p;
    const int l = row & (SEQ - 1);
    const int d0 = col & (HD - 1);
    const float* f = &freqs[(size_t)l * HD + d0];
    float f0 = f[0], f1 = f[1], f2 = f[2], f3 = f[3];
    float4 o;
    o.x = v.x * f0 - v.y * f1;
    o.y = v.y * f0 + v.x * f1;
    o.z = v.z * f2 - v.w * f3;
    o.w = v.w * f2 + v.z * f3;
    *(float4*)p = o;
}

// ---------------------------------------------------------------------------
// prep_kv: split K/V into bf16 hi/lo tiles, in the exact smem layout the
// attention kernel consumes. One block per (kt, h, b) tile; done ONCE
// instead of once per q-block (32x less split work than in-loop).
// Tile layout (u32): [arr: Kh,Kl,Vh,Vl][row 0..31][col 0..63]
//   K: row = d/2, col = key  (word = {K[key][2d'], K[key][2d'+1]})
//   V: row = key/2, col = d  (word = {V[2k'][d],  V[2k'+1][d]})
// ---------------------------------------------------------------------------
__global__ __launch_bounds__(128) void prep_kv()
{
    const int tid = threadIdx.x;
    const int kt = blockIdx.x, h = blockIdx.y, b = blockIdx.z;
    uint32_t* gdst = g_kvsp + (size_t)((b * HEADS + h) * NKT + kt) * 8192;
    const int u  = tid & 31;     // key pair
    const int cq = tid >> 5;     // d quad group
    #pragma unroll
    for (int i = 0; i < 4; i++) {
        const int c = cq * 4 + i * 16;
        const size_t base = (size_t)(b * SEQ + kt * 64 + 2 * u) * QKVN + h * HD + c;
        float4 k0 = *(const float4*)&g_qkv[base + EMB];
        float4 k1 = *(const float4*)&g_qkv[base + EMB + QKVN];
        float4 v0 = *(const float4*)&g_qkv[base + 2 * EMB];
        float4 v1 = *(const float4*)&g_qkv[base + 2 * EMB + QKVN];
        uint32_t ha, la, hb, lb;
        split2(k0.x, k0.y, ha, la);
        split2(k1.x, k1.y, hb, lb);
        *(uint2*)&gdst[0 * 2048 + (c / 2) * 64 + 2 * u] = make_uint2(ha, hb);
        *(uint2*)&gdst[1 * 2048 + (c / 2) * 64 + 2 * u] = make_uint2(la, lb);
        split2(k0.z, k0.w, ha, la);
        split2(k1.z, k1.w, hb, lb);
        *(uint2*)&gdst[0 * 2048 + (c / 2 + 1) * 64 + 2 * u] = make_uint2(ha, hb);
        *(uint2*)&gdst[1 * 2048 + (c / 2 + 1) * 64 + 2 * u] = make_uint2(la, lb);
        uint32_t vh[4], vl[4];
        split2(v0.x, v1.x, vh[0], vl[0]);
        split2(v0.y, v1.y, vh[1], vl[1]);
        split2(v0.z, v1.z, vh[2], vl[2]);
        split2(v0.w, v1.w, vh[3], vl[3]);
        *(uint4*)&gdst[2 * 2048 + u * 64 + c] = make_uint4(vh[0], vh[1], vh[2], vh[3]);
        *(uint4*)&gdst[3 * 2048 + u * 64 + c] = make_uint4(vl[0], vl[1], vl[2], vl[3]);
    }
}

// ---------------------------------------------------------------------------
// nop pad kernels — shift launch order so ncu (-s 5 -c 1) profiles attn_kernel
// ---------------------------------------------------------------------------
__global__ void pad_kernel() { if (threadIdx.x == 0) g_dummy = 1; }

// ---------------------------------------------------------------------------
// Flash attention, 3xBF16 mma.sync m16n8k16, cp.async double-buffered tiles.
// Block: 64 q-rows, one (b,h). 128 threads = 4 warps, warp owns 16 rows.
// smem per stage (u32, row stride 72 pad): Kh[32][72] Kl Vh Vl = 36864B; x2.
// Fragment reads KsT[8ks+tg][8nb+g] are bank-conflict-free (8tg+g distinct).
// ---------------------------------------------------------------------------
#define STG_W 9216          // u32 words per stage (4 * 32 * 72)
__device__ __forceinline__ void issue_tile_copy(const uint32_t* __restrict__ gsrc,
                                                uint32_t sbase_b, int tid)
{
    const int r  = tid >> 2;
    const int qd = tid & 3;
    #pragma unroll
    for (int arr = 0; arr < 4; arr++) {
        const uint32_t* s = gsrc + arr * 2048 + r * 64 + qd * 16;
        uint32_t d = sbase_b + (uint32_t)(arr * 2304 + r * 72 + qd * 16) * 4u;
        #pragma unroll
        for (int j = 0; j < 4; j++)
            cp16(d + j * 16u, s + j * 4);
    }
}

__global__ __launch_bounds__(128) void attn_kernel(const float* __restrict__ bias)
{
    extern __shared__ uint32_t sm[];
    uint32_t smb;   // byte address of dynamic smem for cp.async
    {
        uint64_t t;
        asm("cvta.to.shared.u64 %0, %1;" : "=l"(t) : "l"(sm));
        smb = (uint32_t)t;
    }

    const int tid  = threadIdx.x;
    const int lane = tid & 31;
    const int w    = tid >> 5;
    const int g    = lane >> 2;
    const int tg   = lane & 3;
    const int q0   = blockIdx.x * 64;
    const int h    = blockIdx.y;
    const int b    = blockIdx.z;

    const int rowA = q0 + w * 16 + g;
    const float scale = 0.125f;
    const uint32_t* gtiles = g_kvsp + (size_t)(b * HEADS + h) * NKT * 8192;

    // Q fragments (hi/lo bf16x2), resident
    uint32_t qh[4][4], ql[4][4];
    {
        const float* qA = &g_qkv[(size_t)(b * SEQ + rowA) * QKVN + h * HD];
        const float* qB = qA + (size_t)8 * QKVN;
        #pragma unroll
        for (int ks = 0; ks < 4; ks++) {
            const int d0 = ks * 16 + 2 * tg;
            float2 x0 = *(const float2*)&qA[d0];
            float2 x1 = *(const float2*)&qB[d0];
            float2 x2 = *(const float2*)&qA[d0 + 8];
            float2 x3 = *(const float2*)&qB[d0 + 8];
            split2(x0.x * scale, x0.y * scale, qh[ks][0], ql[ks][0]);
            split2(x1.x * scale, x1.y * scale, qh[ks][1], ql[ks][1]);
            split2(x2.x * scale, x2.y * scale, qh[ks][2], ql[ks][2]);
            split2(x3.x * scale, x3.y * scale, qh[ks][3], ql[ks][3]);
        }
    }

    float o[8][4];
    #pragma unroll
    for (int nb = 0; nb < 8; nb++)
        #pragma unroll
        for (int j = 0; j < 4; j++) o[nb][j] = 0.0f;
    float m0 = -1e30f, m1 = -1e30f, l0 = 0.0f, l1 = 0.0f;

    // prologue: prefetch tile 0 into stage 0
    issue_tile_copy(gtiles, smb, tid);
    cp_commit();

    for (int kt = 0; kt < NKT; kt++) {
        const int cur = kt & 1;
        // prefetch next tile into other stage (overlaps with this tile's compute)
        if (kt + 1 < NKT) {
            issue_tile_copy(gtiles + (size_t)(kt + 1) * 8192,
                            smb + (cur ^ 1) * (STG_W * 4), tid);
            cp_commit();
            asm volatile("cp.async.wait_group 1;");   // tile kt complete
        } else {
            asm volatile("cp.async.wait_group 0;");
        }
        __syncthreads();   // tile kt visible to all warps; prior reads of dst stage done

        const uint32_t* Kh = sm + cur * STG_W;
        const uint32_t* Kl = Kh + 2304;
        const uint32_t* Vh = Kh + 4608;
        const uint32_t* Vl = Kh + 6912;

        // bias prefetch (latency hides behind S-mma below)
        const float* bp = &bias[((size_t)h * SEQ + rowA) * SEQ + kt * 64];
        float2 bb0[8], bb1[8];
        #pragma unroll
        for (int nb = 0; nb < 8; nb++) {
            bb0[nb] = __ldcs((const float2*)(bp + nb * 8 + 2 * tg));
            bb1[nb] = __ldcs((const float2*)(bp + (size_t)8 * SEQ + nb * 8 + 2 * tg));
        }

        // S = Q @ K^T (3xBF16)
        float s[8][4];
        #pragma unroll
        for (int nb = 0; nb < 8; nb++)
            #pragma unroll
            for (int j = 0; j < 4; j++) s[nb][j] = 0.0f;

        #pragma unroll
        for (int ks = 0; ks < 4; ks++) {
            #pragma unroll
            for (int nb = 0; nb < 8; nb++) {
                uint32_t bh[2], bl[2];
                bh[0] = Kh[(8 * ks + tg) * 72 + 8 * nb + g];
                bh[1] = Kh[(8 * ks + tg + 4) * 72 + 8 * nb + g];
                bl[0] = Kl[(8 * ks + tg) * 72 + 8 * nb + g];
                bl[1] = Kl[(8 * ks + tg + 4) * 72 + 8 * nb + g];
                mma_bf16(s[nb], ql[ks], bh);
                mma_bf16(s[nb], qh[ks], bl);
                mma_bf16(s[nb], qh[ks], bh);
            }
        }

        // bias + online softmax
        float mx0 = -1e30f, mx1 = -1e30f;
        #pragma unroll
        for (int nb = 0; nb < 8; nb++) {
            s[nb][0] += bb0[nb].x; s[nb][1] += bb0[nb].y;
            s[nb][2] += bb1[nb].x; s[nb][3] += bb1[nb].y;
            mx0 = fmaxf(mx0, fmaxf(s[nb][0], s[nb][1]));
            mx1 = fmaxf(mx1, fmaxf(s[nb][2], s[nb][3]));
        }
        mx0 = fmaxf(mx0, __shfl_xor_sync(0xffffffffu, mx0, 1));
        mx0 = fmaxf(mx0, __shfl_xor_sync(0xffffffffu, mx0, 2));
        mx1 = fmaxf(mx1, __shfl_xor_sync(0xffffffffu, mx1, 1));
        mx1 = fmaxf(mx1, __shfl_xor_sync(0xffffffffu, mx1, 2));
        const float nm0 = fmaxf(m0, mx0), nm1 = fmaxf(m1, mx1);
        const float al0 = __expf(m0 - nm0), al1 = __expf(m1 - nm1);
        m0 = nm0; m1 = nm1;

        float ts0 = 0.0f, ts1 = 0.0f;
        #pragma unroll
        for (int nb = 0; nb < 8; nb++) {
            s[nb][0] = __expf(s[nb][0] - nm0);
            s[nb][1] = __expf(s[nb][1] - nm0);
            s[nb][2] = __expf(s[nb][2] - nm1);
            s[nb][3] = __expf(s[nb][3] - nm1);
            ts0 += s[nb][0] + s[nb][1];
            ts1 += s[nb][2] + s[nb][3];
        }
        ts0 += __shfl_xor_sync(0xffffffffu, ts0, 1);
        ts0 += __shfl_xor_sync(0xffffffffu, ts0, 2);
        ts1 += __shfl_xor_sync(0xffffffffu, ts1, 1);
        ts1 += __shfl_xor_sync(0xffffffffu, ts1, 2);
        l0 = l0 * al0 + ts0;
        l1 = l1 * al1 + ts1;
        #pragma unroll
        for (int nb = 0; nb < 8; nb++) {
            o[nb][0] *= al0; o[nb][1] *= al0;
            o[nb][2] *= al1; o[nb][3] *= al1;
        }

        // O += P @ V (3xBF16)
        #pragma unroll
        for (int j = 0; j < 4; j++) {
            uint32_t ah[4], al_[4];
            split2(s[2 * j][0],     s[2 * j][1],     ah[0], al_[0]);
            split2(s[2 * j][2],     s[2 * j][3],     ah[1], al_[1]);
            split2(s[2 * j + 1][0], s[2 * j + 1][1], ah[2], al_[2]);
            split2(s[2 * j + 1][2], s[2 * j + 1][3], ah[3], al_[3]);
            #pragma unroll
            for (int nb = 0; nb < 8; nb++) {
                uint32_t vh[2], vl[2];
                vh[0] = Vh[(8 * j + tg) * 72 + 8 * nb + g];
                vh[1] = Vh[(8 * j + tg + 4) * 72 + 8 * nb + g];
                vl[0] = Vl[(8 * j + tg) * 72 + 8 * nb + g];
                vl[1] = Vl[(8 * j + tg + 4) * 72 + 8 * nb + g];
                mma_bf16(o[nb], al_, vh);
                mma_bf16(o[nb], ah,  vl);
                mma_bf16(o[nb], ah,  vh);
            }
        }
        __syncthreads();   // all reads of stage cur done before next prefetch overwrites
    }

    const float inv0 = 1.0f / l0, inv1 = 1.0f / l1;
    float* oA = &g_attn[(size_t)(b * SEQ + rowA) * EMB + h * HD];
    float* oB = oA + (size_t)8 * EMB;
    #pragma unroll
    for (int nb = 0; nb < 8; nb++) {
        *(float2*)(oA + nb * 8 + 2 * tg) = make_float2(o[nb][0] * inv0, o[nb][1] * inv0);
        *(float2*)(oB + nb * 8 + 2 * tg) = make_float2(o[nb][2] * inv1, o[nb][3] * inv1);
    }
}

// ---------------------------------------------------------------------------
__global__ __launch_bounds__(256) void bias_add(float* __restrict__ out,
                                                const float* __restrict__ bproj)
{
    const int idx = blockIdx.x * 256 + threadIdx.x;
    const int c4 = (idx & 255) * 4;
    float4 v = *(float4*)&out[(size_t)idx * 4];
    const float4 bp = *(const float4*)&bproj[c4];
    v.x += bp.x; v.y += bp.y; v.z += bp.z; v.w += bp.w;
    *(float4*)&out[(size_t)idx * 4] = v;
}

extern "C" void kernel_launch(void* const* d_in, const int* in_sizes, int n_in,
                              void* d_out, int out_size)
{
    const float* x      = (const float*)d_in[0];
    const float* freqs  = (const float*)d_in[1];
    const float* bias   = (const float*)d_in[2];
    const float* w_qkv  = (const float*)d_in[3];
    const float* w_proj = (const float*)d_in[4];
    const float* b_proj = (const float*)d_in[5];
    float* out = (float*)d_out;

    float* qkv_ptr;  cudaGetSymbolAddress((void**)&qkv_ptr, g_qkv);
    float* attn_ptr; cudaGetSymbolAddress((void**)&attn_ptr, g_attn);

    const int attn_smem = 2 * STG_W * 4;   // 73728 B (double-buffered)
    cudaFuncSetAttribute(attn_kernel, cudaFuncAttributeMaxDynamicSharedMemorySize, attn_smem);

    // launch order chosen so attn_kernel is the 6th launch (ncu -s 5 -c 1)
    gemm_3xtf32<<<dim3(QKVN / 128, MROWS / 128), 256>>>(x, w_qkv, qkv_ptr, QKVN);   // 1
    rope_kernel<<<(MROWS * 2048 / 4) / 256, 256>>>(freqs);                           // 2
    prep_kv<<<dim3(NKT, HEADS, BATCH), 128>>>();                                     // 3
    pad_kernel<<<1, 32>>>();                                                         // 4
    pad_kernel<<<1, 32>>>();                                                         // 5
    attn_kernel<<<dim3(SEQ / 64, HEADS, BATCH), 128, attn_smem>>>(bias);             // 6
    gemm_3xtf32<<<dim3(EMB / 128, MROWS / 128), 256>>>(attn_ptr, w_proj, out, EMB);  // 7
    bias_add<<<(MROWS * EMB / 4) / 256, 256>>>(out, b_proj);                         // 8
}

// round 8
// speedup vs baseline: 1.4850x; 1.0124x over previous
#include <cuda_runtime.h>
#include <cuda_bf16.h>
#include <mma.h>
#include <cstdint>

using namespace nvcuda;

#define BATCH 2
#define SEQ   2048
#define HEADS 16
#define HD    64
#define EMB   1024
#define MROWS (BATCH*SEQ)
#define QKVN  (3*EMB)
#define NKT   (SEQ/64)           // 32 key tiles

__device__ float g_qkv[(size_t)MROWS * QKVN];   // 50.3 MB
__device__ float g_attn[(size_t)MROWS * EMB];   // 16.8 MB
// Pre-split K/V tiles: [b*H+h][kt][4 arrays: Kh,Kl,Vh,Vl][32 rows][64 cols] u32
__device__ uint32_t g_kvsp[(size_t)BATCH * HEADS * NKT * 4 * 32 * 64];  // 67.1 MB

__device__ __forceinline__ float to_tf32(float x) {
    float y;
    asm("cvt.rna.tf32.f32 %0, %1;" : "=f"(y) : "f"(x));
    return y;
}
__device__ __forceinline__ uint32_t pack_bf16x2(float e0, float e1) {
    uint32_t r;
    asm("cvt.rn.bf16x2.f32 %0, %1, %2;" : "=r"(r) : "f"(e1), "f"(e0));
    return r;
}
__device__ __forceinline__ void split2(float x, float y, uint32_t& hp, uint32_t& lp) {
    float hx = __bfloat162float(__float2bfloat16_rn(x));
    float hy = __bfloat162float(__float2bfloat16_rn(y));
    hp = pack_bf16x2(hx, hy);
    lp = pack_bf16x2(x - hx, y - hy);
}
__device__ __forceinline__ void mma_bf16(float c[4], const uint32_t a[4], const uint32_t b[2]) {
    asm volatile(
        "mma.sync.aligned.m16n8k16.row.col.f32.bf16.bf16.f32 "
        "{%0,%1,%2,%3}, {%4,%5,%6,%7}, {%8,%9}, {%0,%1,%2,%3};"
        : "+f"(c[0]), "+f"(c[1]), "+f"(c[2]), "+f"(c[3])
        : "r"(a[0]), "r"(a[1]), "r"(a[2]), "r"(a[3]), "r"(b[0]), "r"(b[1]));
}
__device__ __forceinline__ void cp16(uint32_t dst, const void* src) {
    asm volatile("cp.async.cg.shared.global [%0], [%1], 16;" :: "r"(dst), "l"(src));
}
__device__ __forceinline__ void cp_commit() {
    asm volatile("cp.async.commit_group;");
}

// ---------------------------------------------------------------------------
// 3xTF32 GEMM (unchanged; measured 369us QKV / ~125us proj)
// ---------------------------------------------------------------------------
__global__ __launch_bounds__(256) void gemm_3xtf32(
    const float* __restrict__ A, const float* __restrict__ B,
    float* __restrict__ C, int Ndim)
{
    __shared__ float AsH[128][24];
    __shared__ float AsL[128][24];
    __shared__ float BsH[16][136];
    __shared__ float BsL[16][136];

    const int tid = threadIdx.x;
    const int warp = tid >> 5;
    const int warp_m = warp >> 2;
    const int warp_n = warp & 3;
    const int m0 = blockIdx.y * 128;
    const int n0 = blockIdx.x * 128;

    wmma::fragment<wmma::accumulator, 16, 16, 8, float> acc[4][2];
    #pragma unroll
    for (int mt = 0; mt < 4; mt++)
        #pragma unroll
        for (int nt = 0; nt < 2; nt++)
            wmma::fill_fragment(acc[mt][nt], 0.0f);

    for (int k0 = 0; k0 < EMB; k0 += 16) {
        {
            const int ar = tid >> 2;
            const int ac = (tid & 3) * 4;
            #pragma unroll
            for (int p = 0; p < 2; p++) {
                const int r = ar + p * 64;
                float4 v = *(const float4*)&A[(size_t)(m0 + r) * EMB + k0 + ac];
                float h0 = to_tf32(v.x), h1 = to_tf32(v.y), h2 = to_tf32(v.z), h3 = to_tf32(v.w);
                AsH[r][ac + 0] = h0; AsL[r][ac + 0] = to_tf32(v.x - h0);
                AsH[r][ac + 1] = h1; AsL[r][ac + 1] = to_tf32(v.y - h1);
                AsH[r][ac + 2] = h2; AsL[r][ac + 2] = to_tf32(v.z - h2);
                AsH[r][ac + 3] = h3; AsL[r][ac + 3] = to_tf32(v.w - h3);
            }
        }
        {
            const int br = tid >> 5;
            const int bc = (tid & 31) * 4;
            #pragma unroll
            for (int p = 0; p < 2; p++) {
                const int r = br + p * 8;
                float4 v = *(const float4*)&B[(size_t)(k0 + r) * Ndim + n0 + bc];
                float h0 = to_tf32(v.x), h1 = to_tf32(v.y), h2 = to_tf32(v.z), h3 = to_tf32(v.w);
                BsH[r][bc + 0] = h0; BsL[r][bc + 0] = to_tf32(v.x - h0);
                BsH[r][bc + 1] = h1; BsL[r][bc + 1] = to_tf32(v.y - h1);
                BsH[r][bc + 2] = h2; BsL[r][bc + 2] = to_tf32(v.z - h2);
                BsH[r][bc + 3] = h3; BsL[r][bc + 3] = to_tf32(v.w - h3);
            }
        }
        __syncthreads();

        #pragma unroll
        for (int ks = 0; ks < 2; ks++) {
            wmma::fragment<wmma::matrix_a, 16, 16, 8, wmma::precision::tf32, wmma::row_major> afH[4], afL[4];
            wmma::fragment<wmma::matrix_b, 16, 16, 8, wmma::precision::tf32, wmma::row_major> bfH[2], bfL[2];
            #pragma unroll
            for (int mt = 0; mt < 4; mt++) {
                wmma::load_matrix_sync(afH[mt], &AsH[warp_m * 64 + mt * 16][ks * 8], 24);
                wmma::load_matrix_sync(afL[mt], &AsL[warp_m * 64 + mt * 16][ks * 8], 24);
            }
            #pragma unroll
            for (int nt = 0; nt < 2; nt++) {
                wmma::load_matrix_sync(bfH[nt], &BsH[ks * 8][warp_n * 32 + nt * 16], 136);
                wmma::load_matrix_sync(bfL[nt], &BsL[ks * 8][warp_n * 32 + nt * 16], 136);
            }
            #pragma unroll
            for (int mt = 0; mt < 4; mt++)
                #pragma unroll
                for (int nt = 0; nt < 2; nt++) {
                    wmma::mma_sync(acc[mt][nt], afL[mt], bfH[nt], acc[mt][nt]);
                    wmma::mma_sync(acc[mt][nt], afH[mt], bfL[nt], acc[mt][nt]);
                    wmma::mma_sync(acc[mt][nt], afH[mt], bfH[nt], acc[mt][nt]);
                }
        }
        __syncthreads();
    }

    #pragma unroll
    for (int mt = 0; mt < 4; mt++)
        #pragma unroll
        for (int nt = 0; nt < 2; nt++)
            wmma::store_matrix_sync(
                &C[(size_t)(m0 + warp_m * 64 + mt * 16) * Ndim + n0 + warp_n * 32 + nt * 16],
                acc[mt][nt], Ndim, wmma::mem_row_major);
}

// ---------------------------------------------------------------------------
// RoPE in place on q,k
// ---------------------------------------------------------------------------
__global__ __launch_bounds__(256) void rope_kernel(const float* __restrict__ freqs)
{
    const int idx = blockIdx.x * 256 + threadIdx.x;
    const int row = idx >> 9;
    const int col = (idx & 511) * 4;
    float* p = &g_qkv[(size_t)row * QKVN + col];
    float4 v = *(float4*)p;
    const int l = row & (SEQ - 1);
    const int d0 = col & (HD - 1);
    const float* f = &freqs[(size_t)l * HD + d0];
    float f0 = f[0], f1 = f[1], f2 = f[2], f3 = f[3];
    float4 o;
    o.x = v.x * f0 - v.y * f1;
    o.y = v.y * f0 + v.x * f1;
    o.z = v.z * f2 - v.w * f3;
    o.w = v.w * f2 + v.z * f3;
    *(float4*)p = o;
}

// ---------------------------------------------------------------------------
// prep_kv: split K/V into bf16 hi/lo tiles once (layout as attn consumes).
//   K: row = d/2, col = key ; V: row = key/2, col = d
// ---------------------------------------------------------------------------
__global__ __launch_bounds__(128) void prep_kv()
{
    const int tid = threadIdx.x;
    const int kt = blockIdx.x, h = blockIdx.y, b = blockIdx.z;
    uint32_t* gdst = g_kvsp + (size_t)((b * HEADS + h) * NKT + kt) * 8192;
    const int u  = tid & 31;     // key pair
    const int cq = tid >> 5;     // d quad group
    #pragma unroll
    for (int i = 0; i < 4; i++) {
        const int c = cq * 4 + i * 16;
        const size_t base = (size_t)(b * SEQ + kt * 64 + 2 * u) * QKVN + h * HD + c;
        float4 k0 = *(const float4*)&g_qkv[base + EMB];
        float4 k1 = *(const float4*)&g_qkv[base + EMB + QKVN];
        float4 v0 = *(const float4*)&g_qkv[base + 2 * EMB];
        float4 v1 = *(const float4*)&g_qkv[base + 2 * EMB + QKVN];
        uint32_t ha, la, hb, lb;
        split2(k0.x, k0.y, ha, la);
        split2(k1.x, k1.y, hb, lb);
        *(uint2*)&gdst[0 * 2048 + (c / 2) * 64 + 2 * u] = make_uint2(ha, hb);
        *(uint2*)&gdst[1 * 2048 + (c / 2) * 64 + 2 * u] = make_uint2(la, lb);
        split2(k0.z, k0.w, ha, la);
        split2(k1.z, k1.w, hb, lb);
        *(uint2*)&gdst[0 * 2048 + (c / 2 + 1) * 64 + 2 * u] = make_uint2(ha, hb);
        *(uint2*)&gdst[1 * 2048 + (c / 2 + 1) * 64 + 2 * u] = make_uint2(la, lb);
        uint32_t vh[4], vl[4];
        split2(v0.x, v1.x, vh[0], vl[0]);
        split2(v0.y, v1.y, vh[1], vl[1]);
        split2(v0.z, v1.z, vh[2], vl[2]);
        split2(v0.w, v1.w, vh[3], vl[3]);
        *(uint4*)&gdst[2 * 2048 + u * 64 + c] = make_uint4(vh[0], vh[1], vh[2], vh[3]);
        *(uint4*)&gdst[3 * 2048 + u * 64 + c] = make_uint4(vl[0], vl[1], vl[2], vl[3]);
    }
}

// ---------------------------------------------------------------------------
// Flash attention, 3xBF16 mma.sync m16n8k16.
// smem (u32 words): K stage0 [0,4608) K stage1 [4608,9216) V [9216,13824)
//   each = {hi[32][72], lo[32][72]}.  55296 B total -> 4 blocks/SM.
// K double-buffered (prefetch t+1 during t); V single-buffered (issued at
// tile start, consumed after softmax — latency hidden by S-mma+softmax).
// ---------------------------------------------------------------------------
#define KSTG_W 4608
#define VOFF_W 9216

__device__ __forceinline__ void issue_half_copy(const uint32_t* __restrict__ gsrc,
                                                uint32_t sbase_b, int tid)
{
    // copies 2 arrays (hi, lo) of [32][64] from gsrc into [32][72]-pitch smem
    const int r  = tid >> 2;
    const int qd = tid & 3;
    #pragma unroll
    for (int arr = 0; arr < 2; arr++) {
        const uint32_t* s = gsrc + arr * 2048 + r * 64 + qd * 16;
        uint32_t d = sbase_b + (uint32_t)(arr * 2304 + r * 72 + qd * 16) * 4u;
        #pragma unroll
        for (int j = 0; j < 4; j++)
            cp16(d + j * 16u, s + j * 4);
    }
}

__global__ __launch_bounds__(128, 4) void attn_kernel(const float* __restrict__ bias)
{
    extern __shared__ uint32_t sm[];
    uint32_t smb;
    {
        uint64_t t;
        asm("cvta.to.shared.u64 %0, %1;" : "=l"(t) : "l"(sm));
        smb = (uint32_t)t;
    }

    const int tid  = threadIdx.x;
    const int lane = tid & 31;
    const int w    = tid >> 5;
    const int g    = lane >> 2;
    const int tg   = lane & 3;
    const int q0   = blockIdx.x * 64;
    const int h    = blockIdx.y;
    const int b    = blockIdx.z;

    const int rowA = q0 + w * 16 + g;
    const float scale = 0.125f;
    const uint32_t* gtiles = g_kvsp + (size_t)(b * HEADS + h) * NKT * 8192;

    // Q fragments (hi/lo bf16x2), resident
    uint32_t qh[4][4], ql[4][4];
    {
        const float* qA = &g_qkv[(size_t)(b * SEQ + rowA) * QKVN + h * HD];
        const float* qB = qA + (size_t)8 * QKVN;
        #pragma unroll
        for (int ks = 0; ks < 4; ks++) {
            const int d0 = ks * 16 + 2 * tg;
            float2 x0 = *(const float2*)&qA[d0];
            float2 x1 = *(const float2*)&qB[d0];
            float2 x2 = *(const float2*)&qA[d0 + 8];
            float2 x3 = *(const float2*)&qB[d0 + 8];
            split2(x0.x * scale, x0.y * scale, qh[ks][0], ql[ks][0]);
            split2(x1.x * scale, x1.y * scale, qh[ks][1], ql[ks][1]);
            split2(x2.x * scale, x2.y * scale, qh[ks][2], ql[ks][2]);
            split2(x3.x * scale, x3.y * scale, qh[ks][3], ql[ks][3]);
        }
    }

    float o[8][4];
    #pragma unroll
    for (int nb = 0; nb < 8; nb++)
        #pragma unroll
        for (int j = 0; j < 4; j++) o[nb][j] = 0.0f;
    float m0 = -1e30f, m1 = -1e30f, l0 = 0.0f, l1 = 0.0f;

    // prologue: prefetch K tile 0 into stage 0
    issue_half_copy(gtiles, smb, tid);            // K arrays are gsrc[0..1]
    cp_commit();                                  // pending: {K0}

    for (int kt = 0; kt < NKT; kt++) {
        const int cur = kt & 1;
        // issue V_t (consumed after softmax)
        issue_half_copy(gtiles + (size_t)kt * 8192 + 4096, smb + VOFF_W * 4, tid);
        cp_commit();                              // pending: {K_t, V_t}
        if (kt + 1 < NKT) {
            issue_half_copy(gtiles + (size_t)(kt + 1) * 8192,
                            smb + (cur ^ 1) * (KSTG_W * 4), tid);
            cp_commit();                          // pending: {K_t, V_t, K_t+1}
            asm volatile("cp.async.wait_group 2;");   // K_t done
        } else {
            asm volatile("cp.async.wait_group 1;");   // K_t done
        }
        __syncthreads();

        const uint32_t* Kh = sm + cur * KSTG_W;
        const uint32_t* Kl = Kh + 2304;

        // S = Q @ K^T (3xBF16)
        float s[8][4];
        #pragma unroll
        for (int nb = 0; nb < 8; nb++)
            #pragma unroll
            for (int j = 0; j < 4; j++) s[nb][j] = 0.0f;

        #pragma unroll
        for (int ks = 0; ks < 4; ks++) {
            #pragma unroll
            for (int nb = 0; nb < 8; nb++) {
                uint32_t bh[2], bl[2];
                bh[0] = Kh[(8 * ks + tg) * 72 + 8 * nb + g];
                bh[1] = Kh[(8 * ks + tg + 4) * 72 + 8 * nb + g];
                bl[0] = Kl[(8 * ks + tg) * 72 + 8 * nb + g];
                bl[1] = Kl[(8 * ks + tg + 4) * 72 + 8 * nb + g];
                mma_bf16(s[nb], ql[ks], bh);
                mma_bf16(s[nb], qh[ks], bl);
                mma_bf16(s[nb], qh[ks], bh);
            }
        }

        // bias (inline) + online softmax
        const float* bp = &bias[((size_t)h * SEQ + rowA) * SEQ + kt * 64];
        float mx0 = -1e30f, mx1 = -1e30f;
        #pragma unroll
        for (int nb = 0; nb < 8; nb++) {
            float2 b0 = __ldcs((const float2*)(bp + nb * 8 + 2 * tg));
            float2 b1 = __ldcs((const float2*)(bp + (size_t)8 * SEQ + nb * 8 + 2 * tg));
            s[nb][0] += b0.x; s[nb][1] += b0.y;
            s[nb][2] += b1.x; s[nb][3] += b1.y;
            mx0 = fmaxf(mx0, fmaxf(s[nb][0], s[nb][1]));
            mx1 = fmaxf(mx1, fmaxf(s[nb][2], s[nb][3]));
        }
        mx0 = fmaxf(mx0, __shfl_xor_sync(0xffffffffu, mx0, 1));
        mx0 = fmaxf(mx0, __shfl_xor_sync(0xffffffffu, mx0, 2));
        mx1 = fmaxf(mx1, __shfl_xor_sync(0xffffffffu, mx1, 1));
        mx1 = fmaxf(mx1, __shfl_xor_sync(0xffffffffu, mx1, 2));
        const float nm0 = fmaxf(m0, mx0), nm1 = fmaxf(m1, mx1);
        const float al0 = __expf(m0 - nm0), al1 = __expf(m1 - nm1);
        m0 = nm0; m1 = nm1;

        float ts0 = 0.0f, ts1 = 0.0f;
        #pragma unroll
        for (int nb = 0; nb < 8; nb++) {
            s[nb][0] = __expf(s[nb][0] - nm0);
            s[nb][1] = __expf(s[nb][1] - nm0);
            s[nb][2] = __expf(s[nb][2] - nm1);
            s[nb][3] = __expf(s[nb][3] - nm1);
            ts0 += s[nb][0] + s[nb][1];
            ts1 += s[nb][2] + s[nb][3];
        }
        ts0 += __shfl_xor_sync(0xffffffffu, ts0, 1);
        ts0 += __shfl_xor_sync(0xffffffffu, ts0, 2);
        ts1 += __shfl_xor_sync(0xffffffffu, ts1, 1);
        ts1 += __shfl_xor_sync(0xffffffffu, ts1, 2);
        l0 = l0 * al0 + ts0;
        l1 = l1 * al1 + ts1;
        #pragma unroll
        for (int nb = 0; nb < 8; nb++) {
            o[nb][0] *= al0; o[nb][1] *= al0;
            o[nb][2] *= al1; o[nb][3] *= al1;
        }

        // wait V_t, then PV
        if (kt + 1 < NKT) {
            asm volatile("cp.async.wait_group 1;");   // V_t done (K_t+1 pending)
        } else {
            asm volatile("cp.async.wait_group 0;");
        }
        __syncthreads();

        const uint32_t* Vh = sm + VOFF_W;
        const uint32_t* Vl = Vh + 2304;

        // O += P @ V (3xBF16)
        #pragma unroll
        for (int j = 0; j < 4; j++) {
            uint32_t ah[4], al_[4];
            split2(s[2 * j][0],     s[2 * j][1],     ah[0], al_[0]);
            split2(s[2 * j][2],     s[2 * j][3],     ah[1], al_[1]);
            split2(s[2 * j + 1][0], s[2 * j + 1][1], ah[2], al_[2]);
            split2(s[2 * j + 1][2], s[2 * j + 1][3], ah[3], al_[3]);
            #pragma unroll
            for (int nb = 0; nb < 8; nb++) {
                uint32_t vh[2], vl[2];
                vh[0] = Vh[(8 * j + tg) * 72 + 8 * nb + g];
                vh[1] = Vh[(8 * j + tg + 4) * 72 + 8 * nb + g];
                vl[0] = Vl[(8 * j + tg) * 72 + 8 * nb + g];
                vl[1] = Vl[(8 * j + tg + 4) * 72 + 8 * nb + g];
                mma_bf16(o[nb], al_, vh);
                mma_bf16(o[nb], ah,  vl);
                mma_bf16(o[nb], ah,  vh);
            }
        }
        __syncthreads();   // V buffer + K stage reads done before next overwrite
    }

    const float inv0 = 1.0f / l0, inv1 = 1.0f / l1;
    float* oA = &g_attn[(size_t)(b * SEQ + rowA) * EMB + h * HD];
    float* oB = oA + (size_t)8 * EMB;
    #pragma unroll
    for (int nb = 0; nb < 8; nb++) {
        *(float2*)(oA + nb * 8 + 2 * tg) = make_float2(o[nb][0] * inv0, o[nb][1] * inv0);
        *(float2*)(oB + nb * 8 + 2 * tg) = make_float2(o[nb][2] * inv1, o[nb][3] * inv1);
    }
}

// ---------------------------------------------------------------------------
__global__ __launch_bounds__(256) void bias_add(float* __restrict__ out,
                                                const float* __restrict__ bproj)
{
    const int idx = blockIdx.x * 256 + threadIdx.x;
    const int c4 = (idx & 255) * 4;
    float4 v = *(float4*)&out[(size_t)idx * 4];
    const float4 bp = *(const float4*)&bproj[c4];
    v.x += bp.x; v.y += bp.y; v.z += bp.z; v.w += bp.w;
    *(float4*)&out[(size_t)idx * 4] = v;
}

extern "C" void kernel_launch(void* const* d_in, const int* in_sizes, int n_in,
                              void* d_out, int out_size)
{
    const float* x      = (const float*)d_in[0];
    const float* freqs  = (const float*)d_in[1];
    const float* bias   = (const float*)d_in[2];
    const float* w_qkv  = (const float*)d_in[3];
    const float* w_proj = (const float*)d_in[4];
    const float* b_proj = (const float*)d_in[5];
    float* out = (float*)d_out;

    float* qkv_ptr;  cudaGetSymbolAddress((void**)&qkv_ptr, g_qkv);
    float* attn_ptr; cudaGetSymbolAddress((void**)&attn_ptr, g_attn);

    const int attn_smem = (2 * KSTG_W + KSTG_W) * 4;   // 55296 B
    cudaFuncSetAttribute(attn_kernel, cudaFuncAttributeMaxDynamicSharedMemorySize, attn_smem);

    // launch order: attn is OUR 4th launch — that's the slot ncu -s 5 -c 1
    // captures (confirmed by grid sizes across rounds 2-7: profiled slot is
    // always our launch #4).
    gemm_3xtf32<<<dim3(QKVN / 128, MROWS / 128), 256>>>(x, w_qkv, qkv_ptr, QKVN);   // 1
    rope_kernel<<<(MROWS * 2048 / 4) / 256, 256>>>(freqs);                           // 2
    prep_kv<<<dim3(NKT, HEADS, BATCH), 128>>>();                                     // 3
    attn_kernel<<<dim3(SEQ / 64, HEADS, BATCH), 128, attn_smem>>>(bias);             // 4
    gemm_3xtf32<<<dim3(EMB / 128, MROWS / 128), 256>>>(attn_ptr, w_proj, out, EMB);  // 5
    bias_add<<<(MROWS * EMB / 4) / 256, 256>>>(out, b_proj);                         // 6
}

// round 9
// speedup vs baseline: 3.1710x; 2.1354x over previous
#include <cuda_runtime.h>
#include <cuda_bf16.h>
#include <cstdint>

#define BATCH 2
#define SEQ   2048
#define HEADS 16
#define HD    64
#define EMB   1024
#define MROWS (BATCH*SEQ)
#define QKVN  (3*EMB)
#define NKT   (SEQ/64)           // 32 key tiles

__device__ float g_qkv[(size_t)MROWS * QKVN];   // 50.3 MB
__device__ float g_attn[(size_t)MROWS * EMB];   // 16.8 MB
// Pre-split K/V tiles: [b*H+h][kt][4 arrays: Kh,Kl,Vh,Vl][32 rows][64 cols] u32
__device__ uint32_t g_kvsp[(size_t)BATCH * HEADS * NKT * 4 * 32 * 64];  // 67.1 MB
__device__ int g_dummy;

__device__ __forceinline__ uint32_t pack_bf16x2(float e0, float e1) {
    uint32_t r;
    asm("cvt.rn.bf16x2.f32 %0, %1, %2;" : "=r"(r) : "f"(e1), "f"(e0));
    return r;
}
__device__ __forceinline__ void split2(float x, float y, uint32_t& hp, uint32_t& lp) {
    float hx = __bfloat162float(__float2bfloat16_rn(x));
    float hy = __bfloat162float(__float2bfloat16_rn(y));
    hp = pack_bf16x2(hx, hy);
    lp = pack_bf16x2(x - hx, y - hy);
}
__device__ __forceinline__ void mma_bf16(float c[4], const uint32_t a[4], const uint32_t b[2]) {
    asm volatile(
        "mma.sync.aligned.m16n8k16.row.col.f32.bf16.bf16.f32 "
        "{%0,%1,%2,%3}, {%4,%5,%6,%7}, {%8,%9}, {%0,%1,%2,%3};"
        : "+f"(c[0]), "+f"(c[1]), "+f"(c[2]), "+f"(c[3])
        : "r"(a[0]), "r"(a[1]), "r"(a[2]), "r"(a[3]), "r"(b[0]), "r"(b[1]));
}
__device__ __forceinline__ void cp16(uint32_t dst, const void* src) {
    asm volatile("cp.async.cg.shared.global [%0], [%1], 16;" :: "r"(dst), "l"(src));
}
__device__ __forceinline__ void cp_commit() {
    asm volatile("cp.async.commit_group;");
}

// ---------------------------------------------------------------------------
// 3xBF16 GEMM: C[M][Ndim] = A[M][1024] * B[1024][Ndim], near-fp32 via hi/lo
// bf16 split (same arithmetic as attention, rel err ~1e-5 per matmul).
// BM=128, BN=128, BK=32; 256 threads / 8 warps; warp tile 64x32.
// smem layout: operand words packed along k-pairs: Ah/Al[kp 16][m 128],
// Bh/Bl[kp 16][n 128], pitch 136 words. Fragment reads [tg(+4)][slab+g] hit
// distinct banks (8tg+g). mma m16n8k16, 3 products: lo*hi + hi*lo + hi*hi.
// ---------------------------------------------------------------------------
__global__ __launch_bounds__(256, 2) void gemm_3xbf16(
    const float* __restrict__ A, const float* __restrict__ B,
    float* __restrict__ C, int Ndim)
{
    __shared__ uint32_t Ah[16][136], Al[16][136];
    __shared__ uint32_t Bh[16][136], Bl[16][136];

    const int tid  = threadIdx.x;
    const int lane = tid & 31;
    const int warp = tid >> 5;
    const int g    = lane >> 2;
    const int tg   = lane & 3;
    const int warp_m = warp >> 2;   // 0..1 -> 64-row slab
    const int warp_n = warp & 3;    // 0..3 -> 32-col slab
    const int m0 = blockIdx.y * 128;
    const int n0 = blockIdx.x * 128;

    float acc[4][4][4];
    #pragma unroll
    for (int mt = 0; mt < 4; mt++)
        #pragma unroll
        for (int nt = 0; nt < 4; nt++)
            #pragma unroll
            for (int c = 0; c < 4; c++) acc[mt][nt][c] = 0.0f;

    for (int k0 = 0; k0 < EMB; k0 += 32) {
        // --- load + split A tile (128 x 32): thread -> row tid>>1, k-half tid&1
        {
            const int m  = tid >> 1;
            const int kh = (tid & 1) * 8;          // k-pair base
            const float* src = &A[(size_t)(m0 + m) * EMB + k0 + kh * 2];
            #pragma unroll
            for (int i = 0; i < 4; i++) {
                float4 v = *(const float4*)&src[i * 4];
                uint32_t h0, l0, h1, l1;
                split2(v.x, v.y, h0, l0);
                split2(v.z, v.w, h1, l1);
                Ah[kh + 2 * i][m]     = h0; Al[kh + 2 * i][m]     = l0;
                Ah[kh + 2 * i + 1][m] = h1; Al[kh + 2 * i + 1][m] = l1;
            }
        }
        // --- load + split B tile (32 x 128): thread -> n-quad, 2 k-pairs
        {
            const int nq  = (lane) * 4;
            const int kp0 = warp;                  // 0..7
            #pragma unroll
            for (int i = 0; i < 2; i++) {
                const int kp = kp0 + i * 8;
                const float* r0 = &B[(size_t)(k0 + 2 * kp) * Ndim + n0 + nq];
                float4 b0 = *(const float4*)r0;
                float4 b1 = *(const float4*)(r0 + Ndim);
                uint32_t h[4], l[4];
                split2(b0.x, b1.x, h[0], l[0]);
                split2(b0.y, b1.y, h[1], l[1]);
                split2(b0.z, b1.z, h[2], l[2]);
                split2(b0.w, b1.w, h[3], l[3]);
                *(uint4*)&Bh[kp][nq] = make_uint4(h[0], h[1], h[2], h[3]);
                *(uint4*)&Bl[kp][nq] = make_uint4(l[0], l[1], l[2], l[3]);
            }
        }
        __syncthreads();

        #pragma unroll
        for (int kc = 0; kc < 2; kc++) {
            uint32_t bh[4][2], bl[4][2];
            #pragma unroll
            for (int nt = 0; nt < 4; nt++) {
                const int nc = warp_n * 32 + nt * 8 + g;
                bh[nt][0] = Bh[kc * 8 + tg][nc];
                bh[nt][1] = Bh[kc * 8 + tg + 4][nc];
                bl[nt][0] = Bl[kc * 8 + tg][nc];
                bl[nt][1] = Bl[kc * 8 + tg + 4][nc];
            }
            #pragma unroll
            for (int mt = 0; mt < 4; mt++) {
                const int mr = warp_m * 64 + mt * 16;
                uint32_t ah[4], al_[4];
                ah[0]  = Ah[kc * 8 + tg][mr + g];
                ah[1]  = Ah[kc * 8 + tg][mr + g + 8];
                ah[2]  = Ah[kc * 8 + tg + 4][mr + g];
                ah[3]  = Ah[kc * 8 + tg + 4][mr + g + 8];
                al_[0] = Al[kc * 8 + tg][mr + g];
                al_[1] = Al[kc * 8 + tg][mr + g + 8];
                al_[2] = Al[kc * 8 + tg + 4][mr + g];
                al_[3] = Al[kc * 8 + tg + 4][mr + g + 8];
                #pragma unroll
                for (int nt = 0; nt < 4; nt++) {
                    mma_bf16(acc[mt][nt], al_,  bh[nt]);
                    mma_bf16(acc[mt][nt], ah,   bl[nt]);
                    mma_bf16(acc[mt][nt], ah,   bh[nt]);
                }
            }
        }
        __syncthreads();
    }

    #pragma unroll
    for (int mt = 0; mt < 4; mt++) {
        const int m = m0 + warp_m * 64 + mt * 16 + g;
        #pragma unroll
        for (int nt = 0; nt < 4; nt++) {
            const int n = n0 + warp_n * 32 + nt * 8 + 2 * tg;
            *(float2*)&C[(size_t)m * Ndim + n]       = make_float2(acc[mt][nt][0], acc[mt][nt][1]);
            *(float2*)&C[(size_t)(m + 8) * Ndim + n] = make_float2(acc[mt][nt][2], acc[mt][nt][3]);
        }
    }
}

// ---------------------------------------------------------------------------
// RoPE in place on q,k
// ---------------------------------------------------------------------------
__global__ __launch_bounds__(256) void rope_kernel(const float* __restrict__ freqs)
{
    const int idx = blockIdx.x * 256 + threadIdx.x;
    const int row = idx >> 9;
    const int col = (idx & 511) * 4;
    float* p = &g_qkv[(size_t)row * QKVN + col];
    float4 v = *(float4*)p;
    const int l = row & (SEQ - 1);
    const int d0 = col & (HD - 1);
    const float* f = &freqs[(size_t)l * HD + d0];
    float f0 = f[0], f1 = f[1], f2 = f[2], f3 = f[3];
    float4 o;
    o.x = v.x * f0 - v.y * f1;
    o.y = v.y * f0 + v.x * f1;
    o.z = v.z * f2 - v.w * f3;
    o.w = v.w * f2 + v.z * f3;
    *(float4*)p = o;
}

// ---------------------------------------------------------------------------
// prep_kv: split K/V into bf16 hi/lo tiles once (layout as attn consumes).
// ---------------------------------------------------------------------------
__global__ __launch_bounds__(128) void prep_kv()
{
    const int tid = threadIdx.x;
    const int kt = blockIdx.x, h = blockIdx.y, b = blockIdx.z;
    uint32_t* gdst = g_kvsp + (size_t)((b * HEADS + h) * NKT + kt) * 8192;
    const int u  = tid & 31;     // key pair
    const int cq = tid >> 5;     // d quad group
    #pragma unroll
    for (int i = 0; i < 4; i++) {
        const int c = cq * 4 + i * 16;
        const size_t base = (size_t)(b * SEQ + kt * 64 + 2 * u) * QKVN + h * HD + c;
        float4 k0 = *(const float4*)&g_qkv[base + EMB];
        float4 k1 = *(const float4*)&g_qkv[base + EMB + QKVN];
        float4 v0 = *(const float4*)&g_qkv[base + 2 * EMB];
        float4 v1 = *(const float4*)&g_qkv[base + 2 * EMB + QKVN];
        uint32_t ha, la, hb, lb;
        split2(k0.x, k0.y, ha, la);
        split2(k1.x, k1.y, hb, lb);
        *(uint2*)&gdst[0 * 2048 + (c / 2) * 64 + 2 * u] = make_uint2(ha, hb);
        *(uint2*)&gdst[1 * 2048 + (c / 2) * 64 + 2 * u] = make_uint2(la, lb);
        split2(k0.z, k0.w, ha, la);
        split2(k1.z, k1.w, hb, lb);
        *(uint2*)&gdst[0 * 2048 + (c / 2 + 1) * 64 + 2 * u] = make_uint2(ha, hb);
        *(uint2*)&gdst[1 * 2048 + (c / 2 + 1) * 64 + 2 * u] = make_uint2(la, lb);
        uint32_t vh[4], vl[4];
        split2(v0.x, v1.x, vh[0], vl[0]);
        split2(v0.y, v1.y, vh[1], vl[1]);
        split2(v0.z, v1.z, vh[2], vl[2]);
        split2(v0.w, v1.w, vh[3], vl[3]);
        *(uint4*)&gdst[2 * 2048 + u * 64 + c] = make_uint4(vh[0], vh[1], vh[2], vh[3]);
        *(uint4*)&gdst[3 * 2048 + u * 64 + c] = make_uint4(vl[0], vl[1], vl[2], vl[3]);
    }
}

// pad kernels shift the ncu capture slot (our 4th launch in the replay stream)
__global__ void pad_kernel() { if (threadIdx.x == 0) g_dummy = 1; }

// ---------------------------------------------------------------------------
// Flash attention, 3xBF16 mma.sync m16n8k16 (unchanged from round 8: 460us).
// ---------------------------------------------------------------------------
#define KSTG_W 4608
#define VOFF_W 9216

__device__ __forceinline__ void issue_half_copy(const uint32_t* __restrict__ gsrc,
                                                uint32_t sbase_b, int tid)
{
    const int r  = tid >> 2;
    const int qd = tid & 3;
    #pragma unroll
    for (int arr = 0; arr < 2; arr++) {
        const uint32_t* s = gsrc + arr * 2048 + r * 64 + qd * 16;
        uint32_t d = sbase_b + (uint32_t)(arr * 2304 + r * 72 + qd * 16) * 4u;
        #pragma unroll
        for (int j = 0; j < 4; j++)
            cp16(d + j * 16u, s + j * 4);
    }
}

__global__ __launch_bounds__(128, 4) void attn_kernel(const float* __restrict__ bias)
{
    extern __shared__ uint32_t sm[];
    uint32_t smb;
    {
        uint64_t t;
        asm("cvta.to.shared.u64 %0, %1;" : "=l"(t) : "l"(sm));
        smb = (uint32_t)t;
    }

    const int tid  = threadIdx.x;
    const int lane = tid & 31;
    const int w    = tid >> 5;
    const int g    = lane >> 2;
    const int tg   = lane & 3;
    const int q0   = blockIdx.x * 64;
    const int h    = blockIdx.y;
    const int b    = blockIdx.z;

    const int rowA = q0 + w * 16 + g;
    const float scale = 0.125f;
    const uint32_t* gtiles = g_kvsp + (size_t)(b * HEADS + h) * NKT * 8192;

    uint32_t qh[4][4], ql[4][4];
    {
        const float* qA = &g_qkv[(size_t)(b * SEQ + rowA) * QKVN + h * HD];
        const float* qB = qA + (size_t)8 * QKVN;
        #pragma unroll
        for (int ks = 0; ks < 4; ks++) {
            const int d0 = ks * 16 + 2 * tg;
            float2 x0 = *(const float2*)&qA[d0];
            float2 x1 = *(const float2*)&qB[d0];
            float2 x2 = *(const float2*)&qA[d0 + 8];
            float2 x3 = *(const float2*)&qB[d0 + 8];
            split2(x0.x * scale, x0.y * scale, qh[ks][0], ql[ks][0]);
            split2(x1.x * scale, x1.y * scale, qh[ks][1], ql[ks][1]);
            split2(x2.x * scale, x2.y * scale, qh[ks][2], ql[ks][2]);
            split2(x3.x * scale, x3.y * scale, qh[ks][3], ql[ks][3]);
        }
    }

    float o[8][4];
    #pragma unroll
    for (int nb = 0; nb < 8; nb++)
        #pragma unroll
        for (int j = 0; j < 4; j++) o[nb][j] = 0.0f;
    float m0 = -1e30f, m1 = -1e30f, l0 = 0.0f, l1 = 0.0f;

    issue_half_copy(gtiles, smb, tid);
    cp_commit();

    for (int kt = 0; kt < NKT; kt++) {
        const int cur = kt & 1;
        issue_half_copy(gtiles + (size_t)kt * 8192 + 4096, smb + VOFF_W * 4, tid);
        cp_commit();
        if (kt + 1 < NKT) {
            issue_half_copy(gtiles + (size_t)(kt + 1) * 8192,
                            smb + (cur ^ 1) * (KSTG_W * 4), tid);
            cp_commit();
            asm volatile("cp.async.wait_group 2;");
        } else {
            asm volatile("cp.async.wait_group 1;");
        }
        __syncthreads();

        const uint32_t* Kh = sm + cur * KSTG_W;
        const uint32_t* Kl = Kh + 2304;

        float s[8][4];
        #pragma unroll
        for (int nb = 0; nb < 8; nb++)
            #pragma unroll
            for (int j = 0; j < 4; j++) s[nb][j] = 0.0f;

        #pragma unroll
        for (int ks = 0; ks < 4; ks++) {
            #pragma unroll
            for (int nb = 0; nb < 8; nb++) {
                uint32_t bh[2], bl[2];
                bh[0] = Kh[(8 * ks + tg) * 72 + 8 * nb + g];
                bh[1] = Kh[(8 * ks + tg + 4) * 72 + 8 * nb + g];
                bl[0] = Kl[(8 * ks + tg) * 72 + 8 * nb + g];
                bl[1] = Kl[(8 * ks + tg + 4) * 72 + 8 * nb + g];
                mma_bf16(s[nb], ql[ks], bh);
                mma_bf16(s[nb], qh[ks], bl);
                mma_bf16(s[nb], qh[ks], bh);
            }
        }

        const float* bp = &bias[((size_t)h * SEQ + rowA) * SEQ + kt * 64];
        float mx0 = -1e30f, mx1 = -1e30f;
        #pragma unroll
        for (int nb = 0; nb < 8; nb++) {
            float2 b0 = __ldcs((const float2*)(bp + nb * 8 + 2 * tg));
            float2 b1 = __ldcs((const float2*)(bp + (size_t)8 * SEQ + nb * 8 + 2 * tg));
            s[nb][0] += b0.x; s[nb][1] += b0.y;
            s[nb][2] += b1.x; s[nb][3] += b1.y;
            mx0 = fmaxf(mx0, fmaxf(s[nb][0], s[nb][1]));
            mx1 = fmaxf(mx1, fmaxf(s[nb][2], s[nb][3]));
        }
        mx0 = fmaxf(mx0, __shfl_xor_sync(0xffffffffu, mx0, 1));
        mx0 = fmaxf(mx0, __shfl_xor_sync(0xffffffffu, mx0, 2));
        mx1 = fmaxf(mx1, __shfl_xor_sync(0xffffffffu, mx1, 1));
        mx1 = fmaxf(mx1, __shfl_xor_sync(0xffffffffu, mx1, 2));
        const float nm0 = fmaxf(m0, mx0), nm1 = fmaxf(m1, mx1);
        const float al0 = __expf(m0 - nm0), al1 = __expf(m1 - nm1);
        m0 = nm0; m1 = nm1;

        float ts0 = 0.0f, ts1 = 0.0f;
        #pragma unroll
        for (int nb = 0; nb < 8; nb++) {
            s[nb][0] = __expf(s[nb][0] - nm0);
            s[nb][1] = __expf(s[nb][1] - nm0);
            s[nb][2] = __expf(s[nb][2] - nm1);
            s[nb][3] = __expf(s[nb][3] - nm1);
            ts0 += s[nb][0] + s[nb][1];
            ts1 += s[nb][2] + s[nb][3];
        }
        ts0 += __shfl_xor_sync(0xffffffffu, ts0, 1);
        ts0 += __shfl_xor_sync(0xffffffffu, ts0, 2);
        ts1 += __shfl_xor_sync(0xffffffffu, ts1, 1);
        ts1 += __shfl_xor_sync(0xffffffffu, ts1, 2);
        l0 = l0 * al0 + ts0;
        l1 = l1 * al1 + ts1;
        #pragma unroll
        for (int nb = 0; nb < 8; nb++) {
            o[nb][0] *= al0; o[nb][1] *= al0;
            o[nb][2] *= al1; o[nb][3] *= al1;
        }

        if (kt + 1 < NKT) {
            asm volatile("cp.async.wait_group 1;");
        } else {
            asm volatile("cp.async.wait_group 0;");
        }
        __syncthreads();

        const uint32_t* Vh = sm + VOFF_W;
        const uint32_t* Vl = Vh + 2304;

        #pragma unroll
        for (int j = 0; j < 4; j++) {
            uint32_t ah[4], al_[4];
            split2(s[2 * j][0],     s[2 * j][1],     ah[0], al_[0]);
            split2(s[2 * j][2],     s[2 * j][3],     ah[1], al_[1]);
            split2(s[2 * j + 1][0], s[2 * j + 1][1], ah[2], al_[2]);
            split2(s[2 * j + 1][2], s[2 * j + 1][3], ah[3], al_[3]);
            #pragma unroll
            for (int nb = 0; nb < 8; nb++) {
                uint32_t vh[2], vl[2];
                vh[0] = Vh[(8 * j + tg) * 72 + 8 * nb + g];
                vh[1] = Vh[(8 * j + tg + 4) * 72 + 8 * nb + g];
                vl[0] = Vl[(8 * j + tg) * 72 + 8 * nb + g];
                vl[1] = Vl[(8 * j + tg + 4) * 72 + 8 * nb + g];
                mma_bf16(o[nb], al_, vh);
                mma_bf16(o[nb], ah,  vl);
                mma_bf16(o[nb], ah,  vh);
            }
        }
        __syncthreads();
    }

    const float inv0 = 1.0f / l0, inv1 = 1.0f / l1;
    float* oA = &g_attn[(size_t)(b * SEQ + rowA) * EMB + h * HD];
    float* oB = oA + (size_t)8 * EMB;
    #pragma unroll
    for (int nb = 0; nb < 8; nb++) {
        *(float2*)(oA + nb * 8 + 2 * tg) = make_float2(o[nb][0] * inv0, o[nb][1] * inv0);
        *(float2*)(oB + nb * 8 + 2 * tg) = make_float2(o[nb][2] * inv1, o[nb][3] * inv1);
    }
}

// ---------------------------------------------------------------------------
__global__ __launch_bounds__(256) void bias_add(float* __restrict__ out,
                                                const float* __restrict__ bproj)
{
    const int idx = blockIdx.x * 256 + threadIdx.x;
    const int c4 = (idx & 255) * 4;
    float4 v = *(float4*)&out[(size_t)idx * 4];
    const float4 bp = *(const float4*)&bproj[c4];
    v.x += bp.x; v.y += bp.y; v.z += bp.z; v.w += bp.w;
    *(float4*)&out[(size_t)idx * 4] = v;
}

extern "C" void kernel_launch(void* const* d_in, const int* in_sizes, int n_in,
                              void* d_out, int out_size)
{
    const float* x      = (const float*)d_in[0];
    const float* freqs  = (const float*)d_in[1];
    const float* bias   = (const float*)d_in[2];
    const float* w_qkv  = (const float*)d_in[3];
    const float* w_proj = (const float*)d_in[4];
    const float* b_proj = (const float*)d_in[5];
    float* out = (float*)d_out;

    float* qkv_ptr;  cudaGetSymbolAddress((void**)&qkv_ptr, g_qkv);
    float* attn_ptr; cudaGetSymbolAddress((void**)&attn_ptr, g_attn);

    const int attn_smem = (2 * KSTG_W + KSTG_W) * 4;   // 55296 B
    cudaFuncSetAttribute(attn_kernel, cudaFuncAttributeMaxDynamicSharedMemorySize, attn_smem);

    // ncu captures our 4th launch in the replay stream -> pads put the new
    // QKV gemm in the profiled slot this round.
    pad_kernel<<<1, 32>>>();                                                         // 1
    pad_kernel<<<1, 32>>>();                                                         // 2
    pad_kernel<<<1, 32>>>();                                                         // 3
    gemm_3xbf16<<<dim3(QKVN / 128, MROWS / 128), 256>>>(x, w_qkv, qkv_ptr, QKVN);   // 4 <- profiled
    rope_kernel<<<(MROWS * 2048 / 4) / 256, 256>>>(freqs);                           // 5
    prep_kv<<<dim3(NKT, HEADS, BATCH), 128>>>();                                     // 6
    attn_kernel<<<dim3(SEQ / 64, HEADS, BATCH), 128, attn_smem>>>(bias);             // 7
    gemm_3xbf16<<<dim3(EMB / 128, MROWS / 128), 256>>>(attn_ptr, w_proj, out, EMB);  // 8
    bias_add<<<(MROWS * EMB / 4) / 256, 256>>>(out, b_proj);                         // 9
}

// round 10
// speedup vs baseline: 3.6719x; 1.1580x over previous
#include <cuda_runtime.h>
#include <cuda_bf16.h>
#include <cstdint>

#define BATCH 2
#define SEQ   2048
#define HEADS 16
#define HD    64
#define EMB   1024
#define MROWS (BATCH*SEQ)
#define QKVN  (3*EMB)
#define NKT   (SEQ/64)           // 32 key tiles

// fp32 qkv (post-rope) — consumed by prep_kv and attn Q-load
__device__ float g_qkv[(size_t)MROWS * QKVN];                           // 50.3 MB
// Pre-split K/V tiles for attention
__device__ uint32_t g_kvsp[(size_t)BATCH * HEADS * NKT * 4 * 32 * 64];  // 67.1 MB
// Pre-split GEMM operands: [kp][M or N] word = {v[2kp][*], v[2kp+1][*]} bf16x2
__device__ uint32_t g_xh[(size_t)(EMB/2) * MROWS],  g_xl[(size_t)(EMB/2) * MROWS];   // 2x8.4MB
__device__ uint32_t g_wqh[(size_t)(EMB/2) * QKVN],  g_wql[(size_t)(EMB/2) * QKVN];   // 2x12.6MB
__device__ uint32_t g_wph[(size_t)(EMB/2) * EMB],   g_wpl[(size_t)(EMB/2) * EMB];    // 2x4.2MB
__device__ uint32_t g_ah[(size_t)(EMB/2) * MROWS],  g_al[(size_t)(EMB/2) * MROWS];   // 2x8.4MB

__device__ __forceinline__ uint32_t pack_bf16x2(float e0, float e1) {
    uint32_t r;
    asm("cvt.rn.bf16x2.f32 %0, %1, %2;" : "=r"(r) : "f"(e1), "f"(e0));
    return r;
}
__device__ __forceinline__ void split2(float x, float y, uint32_t& hp, uint32_t& lp) {
    float hx = __bfloat162float(__float2bfloat16_rn(x));
    float hy = __bfloat162float(__float2bfloat16_rn(y));
    hp = pack_bf16x2(hx, hy);
    lp = pack_bf16x2(x - hx, y - hy);
}
__device__ __forceinline__ void mma_bf16(float c[4], const uint32_t a[4], const uint32_t b[2]) {
    asm volatile(
        "mma.sync.aligned.m16n8k16.row.col.f32.bf16.bf16.f32 "
        "{%0,%1,%2,%3}, {%4,%5,%6,%7}, {%8,%9}, {%0,%1,%2,%3};"
        : "+f"(c[0]), "+f"(c[1]), "+f"(c[2]), "+f"(c[3])
        : "r"(a[0]), "r"(a[1]), "r"(a[2]), "r"(a[3]), "r"(b[0]), "r"(b[1]));
}
__device__ __forceinline__ void cp16(uint32_t dst, const void* src) {
    asm volatile("cp.async.cg.shared.global [%0], [%1], 16;" :: "r"(dst), "l"(src));
}
__device__ __forceinline__ void cp_commit() {
    asm volatile("cp.async.commit_group;");
}

// ---------------------------------------------------------------------------
// prep_a: split fp32 A[M][K] (K=1024) into Ah/Al[kp][M] via smem transpose.
// Block: 64 m x 32 k. grid (K/32, M/64), 256 threads.
// ---------------------------------------------------------------------------
__global__ __launch_bounds__(256) void prep_a(const float* __restrict__ A,
                                              uint32_t* __restrict__ dh,
                                              uint32_t* __restrict__ dl)
{
    __shared__ float stage[64 * 33];
    const int tid = threadIdx.x;
    const int k0 = blockIdx.x * 32;
    const int m0 = blockIdx.y * 64;

    #pragma unroll
    for (int j = 0; j < 2; j++) {
        const int f = tid + j * 256;
        const int r = f >> 3;
        const int c4 = (f & 7) * 4;
        float4 v = *(const float4*)&A[(size_t)(m0 + r) * EMB + k0 + c4];
        stage[r * 33 + c4 + 0] = v.x;
        stage[r * 33 + c4 + 1] = v.y;
        stage[r * 33 + c4 + 2] = v.z;
        stage[r * 33 + c4 + 3] = v.w;
    }
    __syncthreads();

    const int m_l = tid & 63;
    #pragma unroll
    for (int j = 0; j < 4; j++) {
        const int kp_l = (tid >> 6) + j * 4;
        float a = stage[m_l * 33 + 2 * kp_l];
        float b = stage[m_l * 33 + 2 * kp_l + 1];
        uint32_t h, l;
        split2(a, b, h, l);
        dh[(size_t)(k0 / 2 + kp_l) * MROWS + m0 + m_l] = h;
        dl[(size_t)(k0 / 2 + kp_l) * MROWS + m0 + m_l] = l;
    }
}

// ---------------------------------------------------------------------------
// prep_w: split fp32 W[K][N] into Wh/Wl[kp][N] word = {W[2kp][n], W[2kp+1][n]}.
// grid (N/512, K/2), 128 threads x uint4.
// ---------------------------------------------------------------------------
__global__ __launch_bounds__(128) void prep_w(const float* __restrict__ W,
                                              uint32_t* __restrict__ dh,
                                              uint32_t* __restrict__ dl, int N)
{
    const int n  = blockIdx.x * 512 + threadIdx.x * 4;
    const int kp = blockIdx.y;
    float4 r0 = *(const float4*)&W[(size_t)(2 * kp) * N + n];
    float4 r1 = *(const float4*)&W[(size_t)(2 * kp + 1) * N + n];
    uint32_t h[4], l[4];
    split2(r0.x, r1.x, h[0], l[0]);
    split2(r0.y, r1.y, h[1], l[1]);
    split2(r0.z, r1.z, h[2], l[2]);
    split2(r0.w, r1.w, h[3], l[3]);
    *(uint4*)&dh[(size_t)kp * N + n] = make_uint4(h[0], h[1], h[2], h[3]);
    *(uint4*)&dl[(size_t)kp * N + n] = make_uint4(l[0], l[1], l[2], l[3]);
}

// ---------------------------------------------------------------------------
// 3xBF16 GEMM on PRE-SPLIT operands, cp.async double-buffered k-loop.
// C[M][Ndim] = A * B (+ optional fused RoPE epilogue / bias-vector epilogue).
// BM=128 BN=128 BK=32, 256 threads / 8 warps, warp tile 64x32.
// smem (u32 words): stage s at s*8704; within: Ah 0, Al 2176, Bh 4352, Bl 6528;
// row pitch 136 (16 rows x 128 words each). 69632 B total.
// ---------------------------------------------------------------------------
__global__ __launch_bounds__(256, 2) void gemm_sp(
    const uint32_t* __restrict__ AhG, const uint32_t* __restrict__ AlG,
    const uint32_t* __restrict__ BhG, const uint32_t* __restrict__ BlG,
    float* __restrict__ C, int Ndim,
    const float* __restrict__ freqs,   // non-null: fused RoPE on n < 2048
    const float* __restrict__ bvec)    // non-null: fused +bias[n]
{
    extern __shared__ uint32_t sm[];
    uint32_t smb;
    {
        uint64_t t;
        asm("cvta.to.shared.u64 %0, %1;" : "=l"(t) : "l"(sm));
        smb = (uint32_t)t;
    }

    const int tid  = threadIdx.x;
    const int lane = tid & 31;
    const int warp = tid >> 5;
    const int g    = lane >> 2;
    const int tg   = lane & 3;
    const int warp_m = warp >> 2;
    const int warp_n = warp & 3;
    const int m0 = blockIdx.y * 128;
    const int n0 = blockIdx.x * 128;

    // loader mapping: 2048 16B-segments per stage, 8 per thread
    // f = tid + i*256 : arr = f>>9 (0=Ah 1=Al 2=Bh 3=Bl), r = (f>>5)&15, seg = f&31
    float acc[4][4][4];
    #pragma unroll
    for (int mt = 0; mt < 4; mt++)
        #pragma unroll
        for (int nt = 0; nt < 4; nt++)
            #pragma unroll
            for (int c = 0; c < 4; c++) acc[mt][nt][c] = 0.0f;

    const uint32_t* gArr[4] = {AhG, AlG, BhG, BlG};

    // prologue: tile 0 -> stage 0
    {
        #pragma unroll
        for (int i = 0; i < 8; i++) {
            const int f = tid + i * 256;
            const int arr = f >> 9, r = (f >> 5) & 15, seg = f & 31;
            const uint32_t* src = (arr < 2)
                ? gArr[arr] + (size_t)r * MROWS + m0 + seg * 4
                : gArr[arr] + (size_t)r * Ndim + n0 + seg * 4;
            cp16(smb + (uint32_t)(arr * 2176 + r * 136 + seg * 4) * 4u, src);
        }
        cp_commit();
    }

    const int NIT = EMB / 32;   // 32
    for (int it = 0; it < NIT; it++) {
        const int cur = it & 1;
        if (it + 1 < NIT) {
            const int kp0 = (it + 1) * 16;
            const uint32_t sb = smb + (uint32_t)((cur ^ 1) * 8704) * 4u;
            #pragma unroll
            for (int i = 0; i < 8; i++) {
                const int f = tid + i * 256;
                const int arr = f >> 9, r = (f >> 5) & 15, seg = f & 31;
                const uint32_t* src = (arr < 2)
                    ? gArr[arr] + (size_t)(kp0 + r) * MROWS + m0 + seg * 4
                    : gArr[arr] + (size_t)(kp0 + r) * Ndim + n0 + seg * 4;
                cp16(sb + (uint32_t)(arr * 2176 + r * 136 + seg * 4) * 4u, src);
            }
            cp_commit();
            asm volatile("cp.async.wait_group 1;");
        } else {
            asm volatile("cp.async.wait_group 0;");
        }
        __syncthreads();

        const uint32_t* Ah = sm + cur * 8704;
        const uint32_t* Al = Ah + 2176;
        const uint32_t* Bh = Ah + 4352;
        const uint32_t* Bl = Ah + 6528;

        #pragma unroll
        for (int kc = 0; kc < 2; kc++) {
            uint32_t bh[4][2], bl[4][2];
            #pragma unroll
            for (int nt = 0; nt < 4; nt++) {
                const int nc = warp_n * 32 + nt * 8 + g;
                bh[nt][0] = Bh[(kc * 8 + tg) * 136 + nc];
                bh[nt][1] = Bh[(kc * 8 + tg + 4) * 136 + nc];
                bl[nt][0] = Bl[(kc * 8 + tg) * 136 + nc];
                bl[nt][1] = Bl[(kc * 8 + tg + 4) * 136 + nc];
            }
            #pragma unroll
            for (int mt = 0; mt < 4; mt++) {
                const int mr = warp_m * 64 + mt * 16;
                uint32_t ah[4], al_[4];
                ah[0]  = Ah[(kc * 8 + tg) * 136 + mr + g];
                ah[1]  = Ah[(kc * 8 + tg) * 136 + mr + g + 8];
                ah[2]  = Ah[(kc * 8 + tg + 4) * 136 + mr + g];
                ah[3]  = Ah[(kc * 8 + tg + 4) * 136 + mr + g + 8];
                al_[0] = Al[(kc * 8 + tg) * 136 + mr + g];
                al_[1] = Al[(kc * 8 + tg) * 136 + mr + g + 8];
                al_[2] = Al[(kc * 8 + tg + 4) * 136 + mr + g];
                al_[3] = Al[(kc * 8 + tg + 4) * 136 + mr + g + 8];
                #pragma unroll
                for (int nt = 0; nt < 4; nt++) {
                    mma_bf16(acc[mt][nt], al_, bh[nt]);
                    mma_bf16(acc[mt][nt], ah,  bl[nt]);
                    mma_bf16(acc[mt][nt], ah,  bh[nt]);
                }
            }
        }
        __syncthreads();   // all reads of stage cur done before it is re-filled
    }

    // epilogue: optional fused RoPE (QKV) or +bias (proj)
    #pragma unroll
    for (int mt = 0; mt < 4; mt++) {
        const int m = m0 + warp_m * 64 + mt * 16 + g;
        #pragma unroll
        for (int nt = 0; nt < 4; nt++) {
            const int n = n0 + warp_n * 32 + nt * 8 + 2 * tg;
            float a0 = acc[mt][nt][0], a1 = acc[mt][nt][1];
            float a2 = acc[mt][nt][2], a3 = acc[mt][nt][3];
            if (freqs != nullptr) {
                if (n < 2 * EMB) {
                    const int d0 = n & (HD - 1);
                    const float* f0p = &freqs[(size_t)(m & (SEQ - 1)) * HD + d0];
                    const float* f1p = &freqs[(size_t)((m + 8) & (SEQ - 1)) * HD + d0];
                    float f0 = f0p[0], f1 = f0p[1];
                    float e0 = a0 * f0 - a1 * f1;
                    float e1 = a1 * f0 + a0 * f1;
                    a0 = e0; a1 = e1;
                    float h0 = f1p[0], h1 = f1p[1];
                    float e2 = a2 * h0 - a3 * h1;
                    float e3 = a3 * h0 + a2 * h1;
                    a2 = e2; a3 = e3;
                }
            } else if (bvec != nullptr) {
                const float b0 = bvec[n], b1 = bvec[n + 1];
                a0 += b0; a1 += b1; a2 += b0; a3 += b1;
            }
            *(float2*)&C[(size_t)m * Ndim + n]       = make_float2(a0, a1);
            *(float2*)&C[(size_t)(m + 8) * Ndim + n] = make_float2(a2, a3);
        }
    }
}

// ---------------------------------------------------------------------------
// prep_kv: split K/V into bf16 hi/lo tiles once (unchanged).
// ---------------------------------------------------------------------------
__global__ __launch_bounds__(128) void prep_kv()
{
    const int tid = threadIdx.x;
    const int kt = blockIdx.x, h = blockIdx.y, b = blockIdx.z;
    uint32_t* gdst = g_kvsp + (size_t)((b * HEADS + h) * NKT + kt) * 8192;
    const int u  = tid & 31;
    const int cq = tid >> 5;
    #pragma unroll
    for (int i = 0; i < 4; i++) {
        const int c = cq * 4 + i * 16;
        const size_t base = (size_t)(b * SEQ + kt * 64 + 2 * u) * QKVN + h * HD + c;
        float4 k0 = *(const float4*)&g_qkv[base + EMB];
        float4 k1 = *(const float4*)&g_qkv[base + EMB + QKVN];
        float4 v0 = *(const float4*)&g_qkv[base + 2 * EMB];
        float4 v1 = *(const float4*)&g_qkv[base + 2 * EMB + QKVN];
        uint32_t ha, la, hb, lb;
        split2(k0.x, k0.y, ha, la);
        split2(k1.x, k1.y, hb, lb);
        *(uint2*)&gdst[0 * 2048 + (c / 2) * 64 + 2 * u] = make_uint2(ha, hb);
        *(uint2*)&gdst[1 * 2048 + (c / 2) * 64 + 2 * u] = make_uint2(la, lb);
        split2(k0.z, k0.w, ha, la);
        split2(k1.z, k1.w, hb, lb);
        *(uint2*)&gdst[0 * 2048 + (c / 2 + 1) * 64 + 2 * u] = make_uint2(ha, hb);
        *(uint2*)&gdst[1 * 2048 + (c / 2 + 1) * 64 + 2 * u] = make_uint2(la, lb);
        uint32_t vh[4], vl[4];
        split2(v0.x, v1.x, vh[0], vl[0]);
        split2(v0.y, v1.y, vh[1], vl[1]);
        split2(v0.z, v1.z, vh[2], vl[2]);
        split2(v0.w, v1.w, vh[3], vl[3]);
        *(uint4*)&gdst[2 * 2048 + u * 64 + c] = make_uint4(vh[0], vh[1], vh[2], vh[3]);
        *(uint4*)&gdst[3 * 2048 + u * 64 + c] = make_uint4(vl[0], vl[1], vl[2], vl[3]);
    }
}

// ---------------------------------------------------------------------------
// Flash attention (round-8 core, 460us) — epilogue now writes pre-split
// hi/lo operand layout for the proj GEMM: g_ah/g_al[kp][M].
// ---------------------------------------------------------------------------
#define KSTG_W 4608
#define VOFF_W 9216

__device__ __forceinline__ void issue_half_copy(const uint32_t* __restrict__ gsrc,
                                                uint32_t sbase_b, int tid)
{
    const int r  = tid >> 2;
    const int qd = tid & 3;
    #pragma unroll
    for (int arr = 0; arr < 2; arr++) {
        const uint32_t* s = gsrc + arr * 2048 + r * 64 + qd * 16;
        uint32_t d = sbase_b + (uint32_t)(arr * 2304 + r * 72 + qd * 16) * 4u;
        #pragma unroll
        for (int j = 0; j < 4; j++)
            cp16(d + j * 16u, s + j * 4);
    }
}

__global__ __launch_bounds__(128, 4) void attn_kernel(const float* __restrict__ bias)
{
    extern __shared__ uint32_t sm[];
    uint32_t smb;
    {
        uint64_t t;
        asm("cvta.to.shared.u64 %0, %1;" : "=l"(t) : "l"(sm));
        smb = (uint32_t)t;
    }

    const int tid  = threadIdx.x;
    const int lane = tid & 31;
    const int w    = tid >> 5;
    const int g    = lane >> 2;
    const int tg   = lane & 3;
    const int q0   = blockIdx.x * 64;
    const int h    = blockIdx.y;
    const int b    = blockIdx.z;

    const int rowA = q0 + w * 16 + g;
    const float scale = 0.125f;
    const uint32_t* gtiles = g_kvsp + (size_t)(b * HEADS + h) * NKT * 8192;

    uint32_t qh[4][4], ql[4][4];
    {
        const float* qA = &g_qkv[(size_t)(b * SEQ + rowA) * QKVN + h * HD];
        const float* qB = qA + (size_t)8 * QKVN;
        #pragma unroll
        for (int ks = 0; ks < 4; ks++) {
            const int d0 = ks * 16 + 2 * tg;
            float2 x0 = *(const float2*)&qA[d0];
            float2 x1 = *(const float2*)&qB[d0];
            float2 x2 = *(const float2*)&qA[d0 + 8];
            float2 x3 = *(const float2*)&qB[d0 + 8];
            split2(x0.x * scale, x0.y * scale, qh[ks][0], ql[ks][0]);
            split2(x1.x * scale, x1.y * scale, qh[ks][1], ql[ks][1]);
            split2(x2.x * scale, x2.y * scale, qh[ks][2], ql[ks][2]);
            split2(x3.x * scale, x3.y * scale, qh[ks][3], ql[ks][3]);
        }
    }

    float o[8][4];
    #pragma unroll
    for (int nb = 0; nb < 8; nb++)
        #pragma unroll
        for (int j = 0; j < 4; j++) o[nb][j] = 0.0f;
    float m0 = -1e30f, m1 = -1e30f, l0 = 0.0f, l1 = 0.0f;

    issue_half_copy(gtiles, smb, tid);
    cp_commit();

    for (int kt = 0; kt < NKT; kt++) {
        const int cur = kt & 1;
        issue_half_copy(gtiles + (size_t)kt * 8192 + 4096, smb + VOFF_W * 4, tid);
        cp_commit();
        if (kt + 1 < NKT) {
            issue_half_copy(gtiles + (size_t)(kt + 1) * 8192,
                            smb + (cur ^ 1) * (KSTG_W * 4), tid);
            cp_commit();
            asm volatile("cp.async.wait_group 2;");
        } else {
            asm volatile("cp.async.wait_group 1;");
        }
        __syncthreads();

        const uint32_t* Kh = sm + cur * KSTG_W;
        const uint32_t* Kl = Kh + 2304;

        float s[8][4];
        #pragma unroll
        for (int nb = 0; nb < 8; nb++)
            #pragma unroll
            for (int j = 0; j < 4; j++) s[nb][j] = 0.0f;

        #pragma unroll
        for (int ks = 0; ks < 4; ks++) {
            #pragma unroll
            for (int nb = 0; nb < 8; nb++) {
                uint32_t bh[2], bl[2];
                bh[0] = Kh[(8 * ks + tg) * 72 + 8 * nb + g];
                bh[1] = Kh[(8 * ks + tg + 4) * 72 + 8 * nb + g];
                bl[0] = Kl[(8 * ks + tg) * 72 + 8 * nb + g];
                bl[1] = Kl[(8 * ks + tg + 4) * 72 + 8 * nb + g];
                mma_bf16(s[nb], ql[ks], bh);
                mma_bf16(s[nb], qh[ks], bl);
                mma_bf16(s[nb], qh[ks], bh);
            }
        }

        const float* bp = &bias[((size_t)h * SEQ + rowA) * SEQ + kt * 64];
        float mx0 = -1e30f, mx1 = -1e30f;
        #pragma unroll
        for (int nb = 0; nb < 8; nb++) {
            float2 b0 = __ldcs((const float2*)(bp + nb * 8 + 2 * tg));
            float2 b1 = __ldcs((const float2*)(bp + (size_t)8 * SEQ + nb * 8 + 2 * tg));
            s[nb][0] += b0.x; s[nb][1] += b0.y;
            s[nb][2] += b1.x; s[nb][3] += b1.y;
            mx0 = fmaxf(mx0, fmaxf(s[nb][0], s[nb][1]));
            mx1 = fmaxf(mx1, fmaxf(s[nb][2], s[nb][3]));
        }
        mx0 = fmaxf(mx0, __shfl_xor_sync(0xffffffffu, mx0, 1));
        mx0 = fmaxf(mx0, __shfl_xor_sync(0xffffffffu, mx0, 2));
        mx1 = fmaxf(mx1, __shfl_xor_sync(0xffffffffu, mx1, 1));
        mx1 = fmaxf(mx1, __shfl_xor_sync(0xffffffffu, mx1, 2));
        const float nm0 = fmaxf(m0, mx0), nm1 = fmaxf(m1, mx1);
        const float al0 = __expf(m0 - nm0), al1 = __expf(m1 - nm1);
        m0 = nm0; m1 = nm1;

        float ts0 = 0.0f, ts1 = 0.0f;
        #pragma unroll
        for (int nb = 0; nb < 8; nb++) {
            s[nb][0] = __expf(s[nb][0] - nm0);
            s[nb][1] = __expf(s[nb][1] - nm0);
            s[nb][2] = __expf(s[nb][2] - nm1);
            s[nb][3] = __expf(s[nb][3] - nm1);
            ts0 += s[nb][0] + s[nb][1];
            ts1 += s[nb][2] + s[nb][3];
        }
        ts0 += __shfl_xor_sync(0xffffffffu, ts0, 1);
        ts0 += __shfl_xor_sync(0xffffffffu, ts0, 2);
        ts1 += __shfl_xor_sync(0xffffffffu, ts1, 1);
        ts1 += __shfl_xor_sync(0xffffffffu, ts1, 2);
        l0 = l0 * al0 + ts0;
        l1 = l1 * al1 + ts1;
        #pragma unroll
        for (int nb = 0; nb < 8; nb++) {
            o[nb][0] *= al0; o[nb][1] *= al0;
            o[nb][2] *= al1; o[nb][3] *= al1;
        }

        if (kt + 1 < NKT) {
            asm volatile("cp.async.wait_group 1;");
        } else {
            asm volatile("cp.async.wait_group 0;");
        }
        __syncthreads();

        const uint32_t* Vh = sm + VOFF_W;
        const uint32_t* Vl = Vh + 2304;

        #pragma unroll
        for (int j = 0; j < 4; j++) {
            uint32_t ah[4], al_[4];
            split2(s[2 * j][0],     s[2 * j][1],     ah[0], al_[0]);
            split2(s[2 * j][2],     s[2 * j][3],     ah[1], al_[1]);
            split2(s[2 * j + 1][0], s[2 * j + 1][1], ah[2], al_[2]);
            split2(s[2 * j + 1][2], s[2 * j + 1][3], ah[3], al_[3]);
            #pragma unroll
            for (int nb = 0; nb < 8; nb++) {
                uint32_t vh[2], vl[2];
                vh[0] = Vh[(8 * j + tg) * 72 + 8 * nb + g];
                vh[1] = Vh[(8 * j + tg + 4) * 72 + 8 * nb + g];
                vl[0] = Vl[(8 * j + tg) * 72 + 8 * nb + g];
                vl[1] = Vl[(8 * j + tg + 4) * 72 + 8 * nb + g];
                mma_bf16(o[nb], al_, vh);
                mma_bf16(o[nb], ah,  vl);
                mma_bf16(o[nb], ah,  vh);
            }
        }
        __syncthreads();
    }

    // epilogue: normalize + write PRE-SPLIT hi/lo for the proj GEMM
    const float inv0 = 1.0f / l0, inv1 = 1.0f / l1;
    const int mA = b * SEQ + rowA;
    #pragma unroll
    for (int nb = 0; nb < 8; nb++) {
        const int kp = h * 32 + nb * 4 + tg;
        uint32_t hh, ll;
        split2(o[nb][0] * inv0, o[nb][1] * inv0, hh, ll);
        g_ah[(size_t)kp * MROWS + mA] = hh;
        g_al[(size_t)kp * MROWS + mA] = ll;
        split2(o[nb][2] * inv1, o[nb][3] * inv1, hh, ll);
        g_ah[(size_t)kp * MROWS + mA + 8] = hh;
        g_al[(size_t)kp * MROWS + mA + 8] = ll;
    }
}

// ---------------------------------------------------------------------------
extern "C" void kernel_launch(void* const* d_in, const int* in_sizes, int n_in,
                              void* d_out, int out_size)
{
    const float* x      = (const float*)d_in[0];
    const float* freqs  = (const float*)d_in[1];
    const float* bias   = (const float*)d_in[2];
    const float* w_qkv  = (const float*)d_in[3];
    const float* w_proj = (const float*)d_in[4];
    const float* b_proj = (const float*)d_in[5];
    float* out = (float*)d_out;

    float* qkv_ptr;  cudaGetSymbolAddress((void**)&qkv_ptr, g_qkv);
    uint32_t *xh, *xl, *wqh, *wql, *wph, *wpl, *ah, *al;
    cudaGetSymbolAddress((void**)&xh,  g_xh);
    cudaGetSymbolAddress((void**)&xl,  g_xl);
    cudaGetSymbolAddress((void**)&wqh, g_wqh);
    cudaGetSymbolAddress((void**)&wql, g_wql);
    cudaGetSymbolAddress((void**)&wph, g_wph);
    cudaGetSymbolAddress((void**)&wpl, g_wpl);
    cudaGetSymbolAddress((void**)&ah,  g_ah);
    cudaGetSymbolAddress((void**)&al,  g_al);

    const int gemm_smem = 2 * 8704 * 4;                 // 69632 B
    const int attn_smem = (2 * KSTG_W + KSTG_W) * 4;    // 55296 B
    cudaFuncSetAttribute(gemm_sp, cudaFuncAttributeMaxDynamicSharedMemorySize, gemm_smem);
    cudaFuncSetAttribute(attn_kernel, cudaFuncAttributeMaxDynamicSharedMemorySize, attn_smem);

    // ncu captures our 4th launch -> QKV gemm is in the profiled slot.
    prep_a<<<dim3(EMB / 32, MROWS / 64), 256>>>(x, xh, xl);                          // 1
    prep_w<<<dim3(QKVN / 512, EMB / 2), 128>>>(w_qkv, wqh, wql, QKVN);               // 2
    prep_w<<<dim3(EMB / 512, EMB / 2), 128>>>(w_proj, wph, wpl, EMB);                // 3
    gemm_sp<<<dim3(QKVN / 128, MROWS / 128), 256, gemm_smem>>>(                      // 4 <- profiled
        xh, xl, wqh, wql, qkv_ptr, QKVN, freqs, nullptr);
    prep_kv<<<dim3(NKT, HEADS, BATCH), 128>>>();                                     // 5
    attn_kernel<<<dim3(SEQ / 64, HEADS, BATCH), 128, attn_smem>>>(bias);             // 6
    gemm_sp<<<dim3(EMB / 128, MROWS / 128), 256, gemm_smem>>>(                       // 7
        ah, al, wph, wpl, out, EMB, nullptr, b_proj);
}

// round 11
// speedup vs baseline: 3.7501x; 1.0213x over previous
#include <cuda_runtime.h>
#include <cuda_bf16.h>
#include <cstdint>

#define BATCH 2
#define SEQ   2048
#define HEADS 16
#define HD    64
#define EMB   1024
#define MROWS (BATCH*SEQ)
#define QKVN  (3*EMB)
#define NKT   (SEQ/64)           // 32 key tiles

// roped q, fp32 dense [MROWS][EMB]
__device__ float g_q[(size_t)MROWS * EMB];                               // 16.8 MB
// K/V tiles, {hi,lo}-interleaved bf16x2 words:
//   per (b,h,kt) tile 8192 words: K at 0:   ((d/2)*64 + key)*2 + {0,1}
//                                 V at 4096: ((key/2)*64 + d)*2 + {0,1}
__device__ uint32_t g_kvsp[(size_t)BATCH * HEADS * NKT * 8192];          // 67.1 MB
// Pre-split GEMM operands: [kp][M or N] word = {v[2kp][*], v[2kp+1][*]}
__device__ uint32_t g_xh[(size_t)(EMB/2) * MROWS],  g_xl[(size_t)(EMB/2) * MROWS];
__device__ uint32_t g_wqh[(size_t)(EMB/2) * QKVN],  g_wql[(size_t)(EMB/2) * QKVN];
__device__ uint32_t g_wph[(size_t)(EMB/2) * EMB],   g_wpl[(size_t)(EMB/2) * EMB];
__device__ uint32_t g_ah[(size_t)(EMB/2) * MROWS],  g_al[(size_t)(EMB/2) * MROWS];

__device__ __forceinline__ uint32_t pack_bf16x2(float e0, float e1) {
    uint32_t r;
    asm("cvt.rn.bf16x2.f32 %0, %1, %2;" : "=r"(r) : "f"(e1), "f"(e0));
    return r;
}
__device__ __forceinline__ void split2(float x, float y, uint32_t& hp, uint32_t& lp) {
    float hx = __bfloat162float(__float2bfloat16_rn(x));
    float hy = __bfloat162float(__float2bfloat16_rn(y));
    hp = pack_bf16x2(hx, hy);
    lp = pack_bf16x2(x - hx, y - hy);
}
__device__ __forceinline__ void mma_bf16(float c[4], const uint32_t a[4], const uint32_t b[2]) {
    asm volatile(
        "mma.sync.aligned.m16n8k16.row.col.f32.bf16.bf16.f32 "
        "{%0,%1,%2,%3}, {%4,%5,%6,%7}, {%8,%9}, {%0,%1,%2,%3};"
        : "+f"(c[0]), "+f"(c[1]), "+f"(c[2]), "+f"(c[3])
        : "r"(a[0]), "r"(a[1]), "r"(a[2]), "r"(a[3]), "r"(b[0]), "r"(b[1]));
}
__device__ __forceinline__ void cp16(uint32_t dst, const void* src) {
    asm volatile("cp.async.cg.shared.global [%0], [%1], 16;" :: "r"(dst), "l"(src));
}
__device__ __forceinline__ void cp_commit() {
    asm volatile("cp.async.commit_group;");
}

// ---------------------------------------------------------------------------
// prep_a: split fp32 A[M][K] into Ah/Al[kp][M] via smem transpose (unchanged).
// ---------------------------------------------------------------------------
__global__ __launch_bounds__(256) void prep_a(const float* __restrict__ A,
                                              uint32_t* __restrict__ dh,
                                              uint32_t* __restrict__ dl)
{
    __shared__ float stage[64 * 33];
    const int tid = threadIdx.x;
    const int k0 = blockIdx.x * 32;
    const int m0 = blockIdx.y * 64;

    #pragma unroll
    for (int j = 0; j < 2; j++) {
        const int f = tid + j * 256;
        const int r = f >> 3;
        const int c4 = (f & 7) * 4;
        float4 v = *(const float4*)&A[(size_t)(m0 + r) * EMB + k0 + c4];
        stage[r * 33 + c4 + 0] = v.x;
        stage[r * 33 + c4 + 1] = v.y;
        stage[r * 33 + c4 + 2] = v.z;
        stage[r * 33 + c4 + 3] = v.w;
    }
    __syncthreads();

    const int m_l = tid & 63;
    #pragma unroll
    for (int j = 0; j < 4; j++) {
        const int kp_l = (tid >> 6) + j * 4;
        float a = stage[m_l * 33 + 2 * kp_l];
        float b = stage[m_l * 33 + 2 * kp_l + 1];
        uint32_t h, l;
        split2(a, b, h, l);
        dh[(size_t)(k0 / 2 + kp_l) * MROWS + m0 + m_l] = h;
        dl[(size_t)(k0 / 2 + kp_l) * MROWS + m0 + m_l] = l;
    }
}

// ---------------------------------------------------------------------------
// prep_w: split fp32 W[K][N] into Wh/Wl[kp][N] (unchanged).
// ---------------------------------------------------------------------------
__global__ __launch_bounds__(128) void prep_w(const float* __restrict__ W,
                                              uint32_t* __restrict__ dh,
                                              uint32_t* __restrict__ dl, int N)
{
    const int n  = blockIdx.x * 512 + threadIdx.x * 4;
    const int kp = blockIdx.y;
    float4 r0 = *(const float4*)&W[(size_t)(2 * kp) * N + n];
    float4 r1 = *(const float4*)&W[(size_t)(2 * kp + 1) * N + n];
    uint32_t h[4], l[4];
    split2(r0.x, r1.x, h[0], l[0]);
    split2(r0.y, r1.y, h[1], l[1]);
    split2(r0.z, r1.z, h[2], l[2]);
    split2(r0.w, r1.w, h[3], l[3]);
    *(uint4*)&dh[(size_t)kp * N + n] = make_uint4(h[0], h[1], h[2], h[3]);
    *(uint4*)&dl[(size_t)kp * N + n] = make_uint4(l[0], l[1], l[2], l[3]);
}

// ---------------------------------------------------------------------------
// 3xBF16 GEMM on pre-split operands, cp.async double-buffered k-loop.
// mode 0 (proj): C[m][Ndim] = A*B + bvec[n]
// mode 1 (QKV):  q cols -> RoPE -> g_q fp32 ; k cols -> RoPE -> split ->
//                g_kvsp K tiles ; v cols -> split (shfl key-pairing) -> V tiles
// ---------------------------------------------------------------------------
__global__ __launch_bounds__(256, 2) void gemm_sp(
    const uint32_t* __restrict__ AhG, const uint32_t* __restrict__ AlG,
    const uint32_t* __restrict__ BhG, const uint32_t* __restrict__ BlG,
    float* __restrict__ C, int Ndim,
    const float* __restrict__ freqs,
    const float* __restrict__ bvec, int mode)
{
    extern __shared__ uint32_t sm[];
    uint32_t smb;
    {
        uint64_t t;
        asm("cvta.to.shared.u64 %0, %1;" : "=l"(t) : "l"(sm));
        smb = (uint32_t)t;
    }

    const int tid  = threadIdx.x;
    const int lane = tid & 31;
    const int warp = tid >> 5;
    const int g    = lane >> 2;
    const int tg   = lane & 3;
    const int warp_m = warp >> 2;
    const int warp_n = warp & 3;
    const int m0 = blockIdx.y * 128;
    const int n0 = blockIdx.x * 128;

    float acc[4][4][4];
    #pragma unroll
    for (int mt = 0; mt < 4; mt++)
        #pragma unroll
        for (int nt = 0; nt < 4; nt++)
            #pragma unroll
            for (int c = 0; c < 4; c++) acc[mt][nt][c] = 0.0f;

    const uint32_t* gArr[4] = {AhG, AlG, BhG, BlG};

    {
        #pragma unroll
        for (int i = 0; i < 8; i++) {
            const int f = tid + i * 256;
            const int arr = f >> 9, r = (f >> 5) & 15, seg = f & 31;
            const uint32_t* src = (arr < 2)
                ? gArr[arr] + (size_t)r * MROWS + m0 + seg * 4
                : gArr[arr] + (size_t)r * Ndim + n0 + seg * 4;
            cp16(smb + (uint32_t)(arr * 2176 + r * 136 + seg * 4) * 4u, src);
        }
        cp_commit();
    }

    const int NIT = EMB / 32;
    for (int it = 0; it < NIT; it++) {
        const int cur = it & 1;
        if (it + 1 < NIT) {
            const int kp0 = (it + 1) * 16;
            const uint32_t sb = smb + (uint32_t)((cur ^ 1) * 8704) * 4u;
            #pragma unroll
            for (int i = 0; i < 8; i++) {
                const int f = tid + i * 256;
                const int arr = f >> 9, r = (f >> 5) & 15, seg = f & 31;
                const uint32_t* src = (arr < 2)
                    ? gArr[arr] + (size_t)(kp0 + r) * MROWS + m0 + seg * 4
                    : gArr[arr] + (size_t)(kp0 + r) * Ndim + n0 + seg * 4;
                cp16(sb + (uint32_t)(arr * 2176 + r * 136 + seg * 4) * 4u, src);
            }
            cp_commit();
            asm volatile("cp.async.wait_group 1;");
        } else {
            asm volatile("cp.async.wait_group 0;");
        }
        __syncthreads();

        const uint32_t* Ah = sm + cur * 8704;
        const uint32_t* Al = Ah + 2176;
        const uint32_t* Bh = Ah + 4352;
        const uint32_t* Bl = Ah + 6528;

        #pragma unroll
        for (int kc = 0; kc < 2; kc++) {
            uint32_t bh[4][2], bl[4][2];
            #pragma unroll
            for (int nt = 0; nt < 4; nt++) {
                const int nc = warp_n * 32 + nt * 8 + g;
                bh[nt][0] = Bh[(kc * 8 + tg) * 136 + nc];
                bh[nt][1] = Bh[(kc * 8 + tg + 4) * 136 + nc];
                bl[nt][0] = Bl[(kc * 8 + tg) * 136 + nc];
                bl[nt][1] = Bl[(kc * 8 + tg + 4) * 136 + nc];
            }
            #pragma unroll
            for (int mt = 0; mt < 4; mt++) {
                const int mr = warp_m * 64 + mt * 16;
                uint32_t ah[4], al_[4];
                ah[0]  = Ah[(kc * 8 + tg) * 136 + mr + g];
                ah[1]  = Ah[(kc * 8 + tg) * 136 + mr + g + 8];
                ah[2]  = Ah[(kc * 8 + tg + 4) * 136 + mr + g];
                ah[3]  = Ah[(kc * 8 + tg + 4) * 136 + mr + g + 8];
                al_[0] = Al[(kc * 8 + tg) * 136 + mr + g];
                al_[1] = Al[(kc * 8 + tg) * 136 + mr + g + 8];
                al_[2] = Al[(kc * 8 + tg + 4) * 136 + mr + g];
                al_[3] = Al[(kc * 8 + tg + 4) * 136 + mr + g + 8];
                #pragma unroll
                for (int nt = 0; nt < 4; nt++) {
                    mma_bf16(acc[mt][nt], al_, bh[nt]);
                    mma_bf16(acc[mt][nt], ah,  bl[nt]);
                    mma_bf16(acc[mt][nt], ah,  bh[nt]);
                }
            }
        }
        __syncthreads();
    }

    // ---------------- epilogue ----------------
    #pragma unroll
    for (int mt = 0; mt < 4; mt++) {
        const int m = m0 + warp_m * 64 + mt * 16 + g;
        #pragma unroll
        for (int nt = 0; nt < 4; nt++) {
            const int n = n0 + warp_n * 32 + nt * 8 + 2 * tg;
            float a0 = acc[mt][nt][0], a1 = acc[mt][nt][1];
            float a2 = acc[mt][nt][2], a3 = acc[mt][nt][3];
            if (mode == 0) {
                const float b0 = bvec[n], b1 = bvec[n + 1];
                *(float2*)&C[(size_t)m * Ndim + n]       = make_float2(a0 + b0, a1 + b1);
                *(float2*)&C[(size_t)(m + 8) * Ndim + n] = make_float2(a2 + b0, a3 + b1);
            } else {
                const int seq = m & (SEQ - 1);
                const int bb  = m >> 11;               // m / SEQ
                if (n < 2 * EMB) {
                    // RoPE on q,k
                    const int d0 = n & (HD - 1);
                    const float* f0p = &freqs[(size_t)seq * HD + d0];
                    const float* f1p = f0p + (size_t)8 * HD;    // row m+8, same batch
                    float f0 = f0p[0], f1 = f0p[1];
                    float e0 = a0 * f0 - a1 * f1;
                    float e1 = a1 * f0 + a0 * f1;
                    float h0 = f1p[0], h1 = f1p[1];
                    float e2 = a2 * h0 - a3 * h1;
                    float e3 = a3 * h0 + a2 * h1;
                    if (n < EMB) {   // q -> fp32 dense
                        *(float2*)&C[(size_t)m * EMB + n]       = make_float2(e0, e1);
                        *(float2*)&C[(size_t)(m + 8) * EMB + n] = make_float2(e2, e3);
                    } else {         // k -> split tiles
                        const int hh = (n - EMB) >> 6;
                        const int d  = n & 63;
                        const int kt = seq >> 6, key = seq & 63;
                        uint32_t* dst = g_kvsp + ((size_t)(bb * HEADS + hh) * NKT + kt) * 8192;
                        uint32_t hp, lp;
                        split2(e0, e1, hp, lp);
                        *(uint2*)&dst[((d >> 1) * 64 + key) * 2] = make_uint2(hp, lp);
                        split2(e2, e3, hp, lp);
                        *(uint2*)&dst[((d >> 1) * 64 + key + 8) * 2] = make_uint2(hp, lp);
                    }
                } else {             // v -> split tiles (adjacent-key pairing)
                    const int hh = (n - 2 * EMB) >> 6;
                    const int d  = n & 63;
                    const int kt = seq >> 6, key = seq & 63;
                    uint32_t* dst = g_kvsp + ((size_t)(bb * HEADS + hh) * NKT + kt) * 8192 + 4096;
                    float p0 = __shfl_xor_sync(0xffffffffu, a0, 4);
                    float p1 = __shfl_xor_sync(0xffffffffu, a1, 4);
                    float p2 = __shfl_xor_sync(0xffffffffu, a2, 4);
                    float p3 = __shfl_xor_sync(0xffffffffu, a3, 4);
                    const int u0 = key >> 1;
                    uint32_t hp, lp;
                    if ((g & 1) == 0) {
                        split2(a0, p0, hp, lp);
                        *(uint2*)&dst[(u0 * 64 + d) * 2] = make_uint2(hp, lp);
                        split2(a2, p2, hp, lp);
                        *(uint2*)&dst[((u0 + 4) * 64 + d) * 2] = make_uint2(hp, lp);
                    } else {
                        split2(p1, a1, hp, lp);
                        *(uint2*)&dst[(u0 * 64 + d + 1) * 2] = make_uint2(hp, lp);
                        split2(p3, a3, hp, lp);
                        *(uint2*)&dst[((u0 + 4) * 64 + d + 1) * 2] = make_uint2(hp, lp);
                    }
                }
            }
        }
    }
}

// ---------------------------------------------------------------------------
// Flash attention, 3xBF16 m16n8k16. 256 threads, 128 q-rows/block.
// smem (u32 words): K stage0 [0,4608) stage1 [4608,9216) V [9216,13824)
// tile rows pitch 144: word pair {hi,lo} at row*144 + col*2 -> LDS.64 reads.
// ---------------------------------------------------------------------------
#define KSTG_W 4608
#define VOFF_W 9216

__device__ __forceinline__ void copy_tile(const uint32_t* __restrict__ gsrc,
                                          uint32_t sbase_b, int tid)
{
    // 4096 words (32 rows x 128) -> smem pitch 144
    #pragma unroll
    for (int i = 0; i < 4; i++) {
        const int q = tid + i * 256;
        const int r = q >> 5;
        const int c = (q & 31) * 4;
        cp16(sbase_b + (uint32_t)(r * 144 + c) * 4u, gsrc + r * 128 + c);
    }
}

__global__ __launch_bounds__(256, 2) void attn_kernel(const float* __restrict__ bias)
{
    extern __shared__ uint32_t sm[];
    uint32_t smb;
    {
        uint64_t t;
        asm("cvta.to.shared.u64 %0, %1;" : "=l"(t) : "l"(sm));
        smb = (uint32_t)t;
    }

    const int tid  = threadIdx.x;
    const int lane = tid & 31;
    const int w    = tid >> 5;       // warp 0..7
    const int g    = lane >> 2;
    const int tg   = lane & 3;
    const int q0   = blockIdx.x * 128;
    const int h    = blockIdx.y;
    const int b    = blockIdx.z;

    const int rowA = q0 + w * 16 + g;
    const float scale = 0.125f;
    const uint32_t* gtiles = g_kvsp + (size_t)(b * HEADS + h) * NKT * 8192;

    // Q fragments (hi/lo bf16x2), resident
    uint32_t qh[4][4], ql[4][4];
    {
        const float* qA = &g_q[(size_t)(b * SEQ + rowA) * EMB + h * HD];
        const float* qB = qA + (size_t)8 * EMB;
        #pragma unroll
        for (int ks = 0; ks < 4; ks++) {
            const int d0 = ks * 16 + 2 * tg;
            float2 x0 = *(const float2*)&qA[d0];
            float2 x1 = *(const float2*)&qB[d0];
            float2 x2 = *(const float2*)&qA[d0 + 8];
            float2 x3 = *(const float2*)&qB[d0 + 8];
            split2(x0.x * scale, x0.y * scale, qh[ks][0], ql[ks][0]);
            split2(x1.x * scale, x1.y * scale, qh[ks][1], ql[ks][1]);
            split2(x2.x * scale, x2.y * scale, qh[ks][2], ql[ks][2]);
            split2(x3.x * scale, x3.y * scale, qh[ks][3], ql[ks][3]);
        }
    }

    float o[8][4];
    #pragma unroll
    for (int nb = 0; nb < 8; nb++)
        #pragma unroll
        for (int j = 0; j < 4; j++) o[nb][j] = 0.0f;
    float m0 = -1e30f, m1 = -1e30f, l0 = 0.0f, l1 = 0.0f;

    // prologue: K tile 0 -> stage 0
    copy_tile(gtiles, smb, tid);
    cp_commit();

    for (int kt = 0; kt < NKT; kt++) {
        const int cur = kt & 1;
        copy_tile(gtiles + (size_t)kt * 8192 + 4096, smb + VOFF_W * 4, tid);   // V_t
        cp_commit();
        if (kt + 1 < NKT) {
            copy_tile(gtiles + (size_t)(kt + 1) * 8192,
                      smb + (cur ^ 1) * (KSTG_W * 4), tid);                    // K_{t+1}
            cp_commit();
            asm volatile("cp.async.wait_group 2;");   // K_t ready
        } else {
            asm volatile("cp.async.wait_group 1;");
        }
        __syncthreads();

        const uint32_t* Ks = sm + cur * KSTG_W;

        // S = Q @ K^T (3xBF16), {hi,lo} via LDS.64
        float s[8][4];
        #pragma unroll
        for (int nb = 0; nb < 8; nb++)
            #pragma unroll
            for (int j = 0; j < 4; j++) s[nb][j] = 0.0f;

        #pragma unroll
        for (int ks = 0; ks < 4; ks++) {
            #pragma unroll
            for (int nb = 0; nb < 8; nb++) {
                uint2 w0 = *(const uint2*)&Ks[(8 * ks + tg) * 144 + (8 * nb + g) * 2];
                uint2 w1 = *(const uint2*)&Ks[(8 * ks + tg + 4) * 144 + (8 * nb + g) * 2];
                uint32_t bh[2] = {w0.x, w1.x};
                uint32_t bl[2] = {w0.y, w1.y};
                mma_bf16(s[nb], ql[ks], bh);
                mma_bf16(s[nb], qh[ks], bl);
                mma_bf16(s[nb], qh[ks], bh);
            }
        }

        // bias + online softmax
        const float* bp = &bias[((size_t)h * SEQ + rowA) * SEQ + kt * 64];
        float mx0 = -1e30f, mx1 = -1e30f;
        #pragma unroll
        for (int nb = 0; nb < 8; nb++) {
            float2 b0 = __ldcs((const float2*)(bp + nb * 8 + 2 * tg));
            float2 b1 = __ldcs((const float2*)(bp + (size_t)8 * SEQ + nb * 8 + 2 * tg));
            s[nb][0] += b0.x; s[nb][1] += b0.y;
            s[nb][2] += b1.x; s[nb][3] += b1.y;
            mx0 = fmaxf(mx0, fmaxf(s[nb][0], s[nb][1]));
            mx1 = fmaxf(mx1, fmaxf(s[nb][2], s[nb][3]));
        }
        mx0 = fmaxf(mx0, __shfl_xor_sync(0xffffffffu, mx0, 1));
        mx0 = fmaxf(mx0, __shfl_xor_sync(0xffffffffu, mx0, 2));
        mx1 = fmaxf(mx1, __shfl_xor_sync(0xffffffffu, mx1, 1));
        mx1 = fmaxf(mx1, __shfl_xor_sync(0xffffffffu, mx1, 2));
        const float nm0 = fmaxf(m0, mx0), nm1 = fmaxf(m1, mx1);
        const float al0 = __expf(m0 - nm0), al1 = __expf(m1 - nm1);
        m0 = nm0; m1 = nm1;

        float ts0 = 0.0f, ts1 = 0.0f;
        #pragma unroll
        for (int nb = 0; nb < 8; nb++) {
            s[nb][0] = __expf(s[nb][0] - nm0);
            s[nb][1] = __expf(s[nb][1] - nm0);
            s[nb][2] = __expf(s[nb][2] - nm1);
            s[nb][3] = __expf(s[nb][3] - nm1);
            ts0 += s[nb][0] + s[nb][1];
            ts1 += s[nb][2] + s[nb][3];
        }
        ts0 += __shfl_xor_sync(0xffffffffu, ts0, 1);
        ts0 += __shfl_xor_sync(0xffffffffu, ts0, 2);
        ts1 += __shfl_xor_sync(0xffffffffu, ts1, 1);
        ts1 += __shfl_xor_sync(0xffffffffu, ts1, 2);
        l0 = l0 * al0 + ts0;
        l1 = l1 * al1 + ts1;
        #pragma unroll
        for (int nb = 0; nb < 8; nb++) {
            o[nb][0] *= al0; o[nb][1] *= al0;
            o[nb][2] *= al1; o[nb][3] *= al1;
        }

        if (kt + 1 < NKT) {
            asm volatile("cp.async.wait_group 1;");   // V_t ready
        } else {
            asm volatile("cp.async.wait_group 0;");
        }
        __syncthreads();

        const uint32_t* Vs = sm + VOFF_W;

        // O += P @ V (3xBF16)
        #pragma unroll
        for (int j = 0; j < 4; j++) {
            uint32_t ah[4], al_[4];
            split2(s[2 * j][0],     s[2 * j][1],     ah[0], al_[0]);
            split2(s[2 * j][2],     s[2 * j][3],     ah[1], al_[1]);
            split2(s[2 * j + 1][0], s[2 * j + 1][1], ah[2], al_[2]);
            split2(s[2 * j + 1][2], s[2 * j + 1][3], ah[3], al_[3]);
            #pragma unroll
            for (int nb = 0; nb < 8; nb++) {
                uint2 w0 = *(const uint2*)&Vs[(8 * j + tg) * 144 + (8 * nb + g) * 2];
                uint2 w1 = *(const uint2*)&Vs[(8 * j + tg + 4) * 144 + (8 * nb + g) * 2];
                uint32_t vh[2] = {w0.x, w1.x};
                uint32_t vl[2] = {w0.y, w1.y};
                mma_bf16(o[nb], al_, vh);
                mma_bf16(o[nb], ah,  vl);
                mma_bf16(o[nb], ah,  vh);
            }
        }
        __syncthreads();
    }

    // epilogue: normalize + write pre-split proj-A operand
    const float inv0 = 1.0f / l0, inv1 = 1.0f / l1;
    const int mA = b * SEQ + rowA;
    #pragma unroll
    for (int nb = 0; nb < 8; nb++) {
        const int kp = h * 32 + nb * 4 + tg;
        uint32_t hh, ll;
        split2(o[nb][0] * inv0, o[nb][1] * inv0, hh, ll);
        g_ah[(size_t)kp * MROWS + mA] = hh;
        g_al[(size_t)kp * MROWS + mA] = ll;
        split2(o[nb][2] * inv1, o[nb][3] * inv1, hh, ll);
        g_ah[(size_t)kp * MROWS + mA + 8] = hh;
        g_al[(size_t)kp * MROWS + mA + 8] = ll;
    }
}

// ---------------------------------------------------------------------------
extern "C" void kernel_launch(void* const* d_in, const int* in_sizes, int n_in,
                              void* d_out, int out_size)
{
    const float* x      = (const float*)d_in[0];
    const float* freqs  = (const float*)d_in[1];
    const float* bias   = (const float*)d_in[2];
    const float* w_qkv  = (const float*)d_in[3];
    const float* w_proj = (const float*)d_in[4];
    const float* b_proj = (const float*)d_in[5];
    float* out = (float*)d_out;

    float* q_ptr; cudaGetSymbolAddress((void**)&q_ptr, g_q);
    uint32_t *xh, *xl, *wqh, *wql, *wph, *wpl, *ah, *al;
    cudaGetSymbolAddress((void**)&xh,  g_xh);
    cudaGetSymbolAddress((void**)&xl,  g_xl);
    cudaGetSymbolAddress((void**)&wqh, g_wqh);
    cudaGetSymbolAddress((void**)&wql, g_wql);
    cudaGetSymbolAddress((void**)&wph, g_wph);
    cudaGetSymbolAddress((void**)&wpl, g_wpl);
    cudaGetSymbolAddress((void**)&ah,  g_ah);
    cudaGetSymbolAddress((void**)&al,  g_al);

    const int gemm_smem = 2 * 8704 * 4;     // 69632 B
    const int attn_smem = 13824 * 4;        // 55296 B
    cudaFuncSetAttribute(gemm_sp, cudaFuncAttributeMaxDynamicSharedMemorySize, gemm_smem);
    cudaFuncSetAttribute(attn_kernel, cudaFuncAttributeMaxDynamicSharedMemorySize, attn_smem);

    // attn is our 4th launch -> lands in the ncu capture slot
    prep_a<<<dim3(EMB / 32, MROWS / 64), 256>>>(x, xh, xl);                          // 1
    prep_w<<<dim3(QKVN / 512, EMB / 2), 128>>>(w_qkv, wqh, wql, QKVN);               // 2
    gemm_sp<<<dim3(QKVN / 128, MROWS / 128), 256, gemm_smem>>>(                      // 3
        xh, xl, wqh, wql, q_ptr, QKVN, freqs, nullptr, 1);
    attn_kernel<<<dim3(SEQ / 128, HEADS, BATCH), 256, attn_smem>>>(bias);            // 4 <- profiled
    prep_w<<<dim3(EMB / 512, EMB / 2), 128>>>(w_proj, wph, wpl, EMB);                // 5
    gemm_sp<<<dim3(EMB / 128, MROWS / 128), 256, gemm_smem>>>(                       // 6
        ah, al, wph, wpl, out, EMB, nullptr, b_proj, 0);
}